// round 1
// baseline (speedup 1.0000x reference)
#include <cuda_runtime.h>
#include <cstddef>

#define N_NODES 50000
#define N_EDGES 1600000
#define INDIM   256
#define HIDIM   128
#define OUTDIM  64

// ---------------- scratch (allocation-free: __device__ globals) ----------------
__device__ float g_deg [N_NODES];
__device__ float g_dinv[N_NODES];
__device__ float g_g1  [(size_t)N_NODES * HIDIM];   // dinv * (x @ W1)
__device__ float g_S1  [(size_t)N_NODES * HIDIM];   // edge scatter accumulator
__device__ float g_h   [(size_t)N_NODES * HIDIM];   // relu(layer1 out)
__device__ float g_g2  [(size_t)N_NODES * OUTDIM];  // dinv * (h @ W2)
__device__ float g_S2  [(size_t)N_NODES * OUTDIM];

// ---------------- tiny utility kernels ----------------
__global__ void zero_f4(float4* p, size_t n4) {
    size_t i = (size_t)blockIdx.x * blockDim.x + threadIdx.x;
    if (i < n4) p[i] = make_float4(0.f, 0.f, 0.f, 0.f);
}

__global__ void deg_accum(const int* __restrict__ col, float* __restrict__ deg) {
    int e = blockIdx.x * blockDim.x + threadIdx.x;
    if (e < N_EDGES) atomicAdd(&deg[col[e]], 1.0f);
}

__global__ void dinv_kernel(const float* __restrict__ deg, float* __restrict__ dinv) {
    int i = blockIdx.x * blockDim.x + threadIdx.x;
    if (i < N_NODES) dinv[i] = rsqrtf(deg[i] + 1.0f);   // +1 self loop; always > 0
}

// ---------------- tiled fp32 GEMM with dinv row-scale epilogue ----------------
// out[r, :] = dinv[r] * (A[r, :] @ W)   A: n x K (row-major), W: K x M (row-major)
template <int K, int M, int BM, int BK, int TM, int TN>
__global__ void gemm_scale(const float* __restrict__ A, const float* __restrict__ W,
                           const float* __restrict__ dinv, float* __restrict__ out, int n)
{
    constexpr int TX = M / TN;          // threads along N
    constexpr int TY = BM / TM;         // threads along M(rows)
    constexpr int NT = TX * TY;

    __shared__ float As[BM][BK + 4];
    __shared__ float Ws[BK][M];

    const int tid = threadIdx.x;
    const int tx  = tid % TX;
    const int ty  = tid / TX;
    const int rowBase = blockIdx.x * BM;

    float acc[TM][TN];
    #pragma unroll
    for (int i = 0; i < TM; i++)
        #pragma unroll
        for (int j = 0; j < TN; j++) acc[i][j] = 0.f;

    for (int k0 = 0; k0 < K; k0 += BK) {
        // load A tile (BM x BK) via float4
        #pragma unroll
        for (int i = tid * 4; i < BM * BK; i += NT * 4) {
            int r = i / BK, c = i % BK;
            int gr = rowBase + r;
            float4 v = make_float4(0.f, 0.f, 0.f, 0.f);
            if (gr < n)
                v = *reinterpret_cast<const float4*>(&A[(size_t)gr * K + k0 + c]);
            As[r][c]     = v.x;
            As[r][c + 1] = v.y;
            As[r][c + 2] = v.z;
            As[r][c + 3] = v.w;
        }
        // load W tile (BK x M) via float4
        #pragma unroll
        for (int i = tid * 4; i < BK * M; i += NT * 4) {
            int r = i / M, c = i % M;
            *reinterpret_cast<float4*>(&Ws[r][c]) =
                *reinterpret_cast<const float4*>(&W[(size_t)(k0 + r) * M + c]);
        }
        __syncthreads();

        #pragma unroll
        for (int kk = 0; kk < BK; kk++) {
            float a[TM], b[TN];
            #pragma unroll
            for (int i = 0; i < TM; i++) a[i] = As[ty * TM + i][kk];
            #pragma unroll
            for (int j = 0; j < TN; j++) b[j] = Ws[kk][tx * TN + j];
            #pragma unroll
            for (int i = 0; i < TM; i++)
                #pragma unroll
                for (int j = 0; j < TN; j++) acc[i][j] = fmaf(a[i], b[j], acc[i][j]);
        }
        __syncthreads();
    }

    #pragma unroll
    for (int i = 0; i < TM; i++) {
        int gr = rowBase + ty * TM + i;
        if (gr < n) {
            float s = dinv[gr];
            #pragma unroll
            for (int j = 0; j < TN; j += 4) {
                float4 v;
                v.x = acc[i][j]     * s;
                v.y = acc[i][j + 1] * s;
                v.z = acc[i][j + 2] * s;
                v.w = acc[i][j + 3] * s;
                *reinterpret_cast<float4*>(&out[(size_t)gr * M + tx * TN + j]) = v;
            }
        }
    }
}

// ---------------- edge scatter: S[col] += g[row]  (per-edge, vectorized red) ----
template <int F>
__global__ void scatter_edges(const int* __restrict__ ei, const float* __restrict__ g,
                              float* __restrict__ S)
{
    constexpr int VT = F / 4;                  // threads per edge
    const int lane = threadIdx.x % VT;
    const int epb  = 256 / VT;                 // edges per block
    const long long e = (long long)blockIdx.x * epb + threadIdx.x / VT;
    if (e >= N_EDGES) return;

    const int row = __ldg(&ei[e]);
    const int col = __ldg(&ei[(size_t)N_EDGES + e]);

    float4 v = *reinterpret_cast<const float4*>(&g[(size_t)row * F + lane * 4]);
    float* dst = &S[(size_t)col * F + lane * 4];
    asm volatile("red.global.add.v4.f32 [%0], {%1, %2, %3, %4};"
                 :: "l"(dst), "f"(v.x), "f"(v.y), "f"(v.z), "f"(v.w)
                 : "memory");
}

// ---------------- fused combine: out = [relu](dinv[i]*(S+g) + b) ----------------
template <int F, bool RELU>
__global__ void combine(const float4* __restrict__ S, const float4* __restrict__ g,
                        const float* __restrict__ dinv, const float4* __restrict__ b,
                        float4* __restrict__ out)
{
    constexpr int F4 = F / 4;
    size_t idx = (size_t)blockIdx.x * blockDim.x + threadIdx.x;
    if (idx >= (size_t)N_NODES * F4) return;
    int i = (int)(idx / F4);
    int f = (int)(idx % F4);
    float d  = __ldg(&dinv[i]);
    float4 s  = S[idx];
    float4 gg = g[idx];
    float4 bb = __ldg(&b[f]);
    float4 r;
    r.x = fmaf(d, s.x + gg.x, bb.x);
    r.y = fmaf(d, s.y + gg.y, bb.y);
    r.z = fmaf(d, s.z + gg.z, bb.z);
    r.w = fmaf(d, s.w + gg.w, bb.w);
    if (RELU) {
        r.x = fmaxf(r.x, 0.f); r.y = fmaxf(r.y, 0.f);
        r.z = fmaxf(r.z, 0.f); r.w = fmaxf(r.w, 0.f);
    }
    out[idx] = r;
}

// ---------------- launch ----------------
extern "C" void kernel_launch(void* const* d_in, const int* in_sizes, int n_in,
                              void* d_out, int out_size)
{
    const float* x  = (const float*)d_in[0];           // [N, 256]
    const int*   ei = (const int*)  d_in[1];           // [2, E]
    const float* W1 = (const float*)d_in[2];           // [256, 128]
    const float* b1 = (const float*)d_in[3];           // [128]
    const float* W2 = (const float*)d_in[4];           // [128, 64]
    const float* b2 = (const float*)d_in[5];           // [64]
    float* out = (float*)d_out;                        // [N, 64]

    float *deg, *dinv, *g1, *S1, *h, *g2, *S2;
    cudaGetSymbolAddress((void**)&deg,  g_deg);
    cudaGetSymbolAddress((void**)&dinv, g_dinv);
    cudaGetSymbolAddress((void**)&g1,   g_g1);
    cudaGetSymbolAddress((void**)&S1,   g_S1);
    cudaGetSymbolAddress((void**)&h,    g_h);
    cudaGetSymbolAddress((void**)&g2,   g_g2);
    cudaGetSymbolAddress((void**)&S2,   g_S2);

    const int T = 256;

    // degree (edge count per dst; +1 self loop folded into rsqrt)
    {
        size_t n4 = N_NODES / 4;
        zero_f4<<<(int)((n4 + T - 1) / T), T>>>((float4*)deg, n4);
    }
    deg_accum<<<(N_EDGES + T - 1) / T, T>>>(ei + N_EDGES, deg);
    dinv_kernel<<<(N_NODES + T - 1) / T, T>>>(deg, dinv);

    // ---- layer 1 ----
    // g1 = dinv * (x @ W1)
    gemm_scale<INDIM, HIDIM, 64, 32, 4, 8>
        <<<(N_NODES + 63) / 64, 256>>>(x, W1, dinv, g1, N_NODES);
    {
        size_t n4 = (size_t)N_NODES * HIDIM / 4;
        zero_f4<<<(int)((n4 + T - 1) / T), T>>>((float4*)S1, n4);
    }
    // S1[col] += g1[row]  (warp per edge, 32 lanes x float4 = 128 floats)
    scatter_edges<HIDIM><<<(N_EDGES + 7) / 8, 256>>>(ei, g1, S1);
    // h = relu(dinv*(S1+g1) + b1)
    {
        size_t n4 = (size_t)N_NODES * HIDIM / 4;
        combine<HIDIM, true><<<(int)((n4 + T - 1) / T), T>>>(
            (const float4*)S1, (const float4*)g1, dinv, (const float4*)b1, (float4*)h);
    }

    // ---- layer 2 ----
    gemm_scale<HIDIM, OUTDIM, 64, 32, 4, 4>
        <<<(N_NODES + 63) / 64, 256>>>(h, W2, dinv, g2, N_NODES);
    {
        size_t n4 = (size_t)N_NODES * OUTDIM / 4;
        zero_f4<<<(int)((n4 + T - 1) / T), T>>>((float4*)S2, n4);
    }
    scatter_edges<OUTDIM><<<(N_EDGES + 15) / 16, 256>>>(ei, g2, S2);
    {
        size_t n4 = (size_t)N_NODES * OUTDIM / 4;
        combine<OUTDIM, false><<<(int)((n4 + T - 1) / T), T>>>(
            (const float4*)S2, (const float4*)g2, dinv, (const float4*)b2, (float4*)out);
    }
}

// round 2
// speedup vs baseline: 1.4094x; 1.4094x over previous
#include <cuda_runtime.h>
#include <cstddef>

#define N_NODES 50000
#define N_EDGES 1600000
#define INDIM   256
#define HIDIM   128
#define OUTDIM  64

// ---------------- scratch (allocation-free: __device__ globals) ----------------
__device__ int   g_degi  [N_NODES];
__device__ int   g_cur   [N_NODES];
__device__ int   g_rowptr[N_NODES + 1];
__device__ int   g_csr   [N_EDGES];
__device__ float g_dinv  [N_NODES];
__device__ float g_g1    [(size_t)N_NODES * HIDIM];   // dinv * (x @ W1)
__device__ float g_h     [(size_t)N_NODES * HIDIM];   // relu(layer1 out)
__device__ float g_g2    [(size_t)N_NODES * OUTDIM];  // dinv * (h @ W2)

// ---------------- tiny utility kernels ----------------
__global__ void zero_i(int* p, int n) {
    int i = blockIdx.x * blockDim.x + threadIdx.x;
    if (i < n) p[i] = 0;
}

__global__ void deg_accum(const int* __restrict__ col, int* __restrict__ degi) {
    int e = blockIdx.x * blockDim.x + threadIdx.x;
    if (e < N_EDGES) atomicAdd(&degi[col[e]], 1);
}

__global__ void dinv_kernel(const int* __restrict__ degi, float* __restrict__ dinv) {
    int i = blockIdx.x * blockDim.x + threadIdx.x;
    if (i < N_NODES) dinv[i] = rsqrtf((float)degi[i] + 1.0f);   // +1 self loop
}

// single-block exclusive prefix scan of degi -> rowptr  (1024 threads)
__global__ void scan_kernel(const int* __restrict__ degi, int* __restrict__ rowptr) {
    __shared__ int sh[1024];
    const int tid = threadIdx.x;
    const int CH  = (N_NODES + 1023) / 1024;   // 49
    const int base = tid * CH;
    int s = 0;
    for (int i = 0; i < CH; i++) {
        int k = base + i;
        if (k < N_NODES) s += degi[k];
    }
    sh[tid] = s;
    __syncthreads();
    // Hillis-Steele inclusive scan
    for (int off = 1; off < 1024; off <<= 1) {
        int v = (tid >= off) ? sh[tid - off] : 0;
        __syncthreads();
        sh[tid] += v;
        __syncthreads();
    }
    int run = (tid == 0) ? 0 : sh[tid - 1];    // exclusive
    for (int i = 0; i < CH; i++) {
        int k = base + i;
        if (k < N_NODES) { rowptr[k] = run; run += degi[k]; }
    }
    if (tid == 1023) rowptr[N_NODES] = run;
}

__global__ void csr_fill(const int* __restrict__ ei, const int* __restrict__ rowptr,
                         int* __restrict__ cur, int* __restrict__ csr) {
    int e = blockIdx.x * blockDim.x + threadIdx.x;
    if (e >= N_EDGES) return;
    int row = ei[e];
    int col = ei[(size_t)N_EDGES + e];
    int pos = rowptr[col] + atomicAdd(&cur[col], 1);
    csr[pos] = row;
}

// ---------------- tiled fp32 GEMM with dinv row-scale epilogue ----------------
// out[r, :] = dinv[r] * (A[r, :] @ W)   A: n x K row-major, W: K x M row-major
// BM=128, BK=16, 256 threads, TM x TN register tile, A transposed in smem.
template <int K, int M, int TM, int TN>
__global__ void __launch_bounds__(256, 2)
gemm_scale(const float* __restrict__ A, const float* __restrict__ W,
           const float* __restrict__ dinv, float* __restrict__ out, int n)
{
    constexpr int BM = 128;
    constexpr int BK = 16;
    constexpr int TX = M / TN;    // threads along cols
    constexpr int TY = BM / TM;   // threads along rows
    static_assert(TX * TY == 256, "thread count");

    __shared__ float As[BK][BM];  // transposed A tile
    __shared__ float Ws[BK][M];

    const int tid = threadIdx.x;
    const int tx  = tid % TX;
    const int ty  = tid / TX;
    const int rowBase = blockIdx.x * BM;

    float acc[TM][TN];
    #pragma unroll
    for (int i = 0; i < TM; i++)
        #pragma unroll
        for (int j = 0; j < TN; j++) acc[i][j] = 0.f;

    constexpr int AF4 = BM * BK / 4;   // float4 loads for A tile
    constexpr int WF4 = BK * M  / 4;

    for (int k0 = 0; k0 < K; k0 += BK) {
        // A tile: coalesced float4 global reads, transposed smem writes
        #pragma unroll
        for (int i = tid; i < AF4; i += 256) {
            int r  = i / (BK / 4);
            int c4 = i % (BK / 4);
            int gr = rowBase + r;
            float4 v = make_float4(0.f, 0.f, 0.f, 0.f);
            if (gr < n)
                v = *reinterpret_cast<const float4*>(&A[(size_t)gr * K + k0 + c4 * 4]);
            As[c4 * 4 + 0][r] = v.x;
            As[c4 * 4 + 1][r] = v.y;
            As[c4 * 4 + 2][r] = v.z;
            As[c4 * 4 + 3][r] = v.w;
        }
        // W tile: straight copy
        #pragma unroll
        for (int i = tid; i < WF4; i += 256) {
            int r = i / (M / 4);
            int c = i % (M / 4);
            reinterpret_cast<float4*>(&Ws[r][0])[c] =
                *reinterpret_cast<const float4*>(&W[(size_t)(k0 + r) * M + c * 4]);
        }
        __syncthreads();

        #pragma unroll
        for (int kk = 0; kk < BK; kk++) {
            float a[TM], b[TN];
            #pragma unroll
            for (int i = 0; i < TM; i += 4)
                *reinterpret_cast<float4*>(&a[i]) =
                    *reinterpret_cast<const float4*>(&As[kk][ty * TM + i]);
            #pragma unroll
            for (int j = 0; j < TN; j += 4)
                *reinterpret_cast<float4*>(&b[j]) =
                    *reinterpret_cast<const float4*>(&Ws[kk][tx * TN + j]);
            #pragma unroll
            for (int i = 0; i < TM; i++)
                #pragma unroll
                for (int j = 0; j < TN; j++)
                    acc[i][j] = fmaf(a[i], b[j], acc[i][j]);
        }
        __syncthreads();
    }

    #pragma unroll
    for (int i = 0; i < TM; i++) {
        int gr = rowBase + ty * TM + i;
        if (gr < n) {
            float s = dinv[gr];
            #pragma unroll
            for (int j = 0; j < TN; j += 4) {
                float4 v;
                v.x = acc[i][j]     * s;
                v.y = acc[i][j + 1] * s;
                v.z = acc[i][j + 2] * s;
                v.w = acc[i][j + 3] * s;
                *reinterpret_cast<float4*>(&out[(size_t)gr * M + tx * TN + j]) = v;
            }
        }
    }
}

// ---------------- CSR gather-aggregate, fused epilogue ----------------
// out[c] = [relu]( dinv[c] * (sum_{r in N(c)} g[r] + g[c]) + b )
// F=128: one warp per node (32 lanes x float4).
template <bool RELU>
__global__ void aggregate128(const int* __restrict__ rowptr, const int* __restrict__ csr,
                             const float4* __restrict__ G, const float* __restrict__ dinv,
                             const float4* __restrict__ bias, float4* __restrict__ out)
{
    const int gw   = (blockIdx.x * blockDim.x + threadIdx.x) >> 5;  // node
    const int lane = threadIdx.x & 31;

    float4 acc = G[(size_t)gw * 32 + lane];  // self-loop term
    const int start = rowptr[gw];
    const int end   = rowptr[gw + 1];

    for (int p = start; p < end; p += 32) {
        const int m = min(32, end - p);
        int idx = (lane < m) ? csr[p + lane] : 0;
        int j = 0;
        for (; j + 4 <= m; j += 4) {
            int r0 = __shfl_sync(0xffffffffu, idx, j + 0);
            int r1 = __shfl_sync(0xffffffffu, idx, j + 1);
            int r2 = __shfl_sync(0xffffffffu, idx, j + 2);
            int r3 = __shfl_sync(0xffffffffu, idx, j + 3);
            float4 v0 = G[(size_t)r0 * 32 + lane];
            float4 v1 = G[(size_t)r1 * 32 + lane];
            float4 v2 = G[(size_t)r2 * 32 + lane];
            float4 v3 = G[(size_t)r3 * 32 + lane];
            acc.x += v0.x + v1.x + v2.x + v3.x;
            acc.y += v0.y + v1.y + v2.y + v3.y;
            acc.z += v0.z + v1.z + v2.z + v3.z;
            acc.w += v0.w + v1.w + v2.w + v3.w;
        }
        for (; j < m; j++) {
            int r = __shfl_sync(0xffffffffu, idx, j);
            float4 v = G[(size_t)r * 32 + lane];
            acc.x += v.x; acc.y += v.y; acc.z += v.z; acc.w += v.w;
        }
    }

    const float d = dinv[gw];
    float4 bb = bias[lane];
    float4 r;
    r.x = fmaf(d, acc.x, bb.x);
    r.y = fmaf(d, acc.y, bb.y);
    r.z = fmaf(d, acc.z, bb.z);
    r.w = fmaf(d, acc.w, bb.w);
    if (RELU) {
        r.x = fmaxf(r.x, 0.f); r.y = fmaxf(r.y, 0.f);
        r.z = fmaxf(r.z, 0.f); r.w = fmaxf(r.w, 0.f);
    }
    out[(size_t)gw * 32 + lane] = r;
}

// F=64: half-warp per node (16 lanes x float4).
template <bool RELU>
__global__ void aggregate64(const int* __restrict__ rowptr, const int* __restrict__ csr,
                            const float4* __restrict__ G, const float* __restrict__ dinv,
                            const float4* __restrict__ bias, float4* __restrict__ out)
{
    const int gn   = (blockIdx.x * blockDim.x + threadIdx.x) >> 4;  // node
    const int lane = threadIdx.x & 15;

    float4 acc = G[(size_t)gn * 16 + lane];  // self-loop term
    const int start = rowptr[gn];
    const int end   = rowptr[gn + 1];

    for (int p = start; p < end; p += 16) {
        const int m = min(16, end - p);
        int idx = (lane < m) ? csr[p + lane] : 0;
        int j = 0;
        for (; j + 4 <= m; j += 4) {
            int r0 = __shfl_sync(0xffffffffu, idx, j + 0, 16);
            int r1 = __shfl_sync(0xffffffffu, idx, j + 1, 16);
            int r2 = __shfl_sync(0xffffffffu, idx, j + 2, 16);
            int r3 = __shfl_sync(0xffffffffu, idx, j + 3, 16);
            float4 v0 = G[(size_t)r0 * 16 + lane];
            float4 v1 = G[(size_t)r1 * 16 + lane];
            float4 v2 = G[(size_t)r2 * 16 + lane];
            float4 v3 = G[(size_t)r3 * 16 + lane];
            acc.x += v0.x + v1.x + v2.x + v3.x;
            acc.y += v0.y + v1.y + v2.y + v3.y;
            acc.z += v0.z + v1.z + v2.z + v3.z;
            acc.w += v0.w + v1.w + v2.w + v3.w;
        }
        for (; j < m; j++) {
            int r = __shfl_sync(0xffffffffu, idx, j, 16);
            float4 v = G[(size_t)r * 16 + lane];
            acc.x += v.x; acc.y += v.y; acc.z += v.z; acc.w += v.w;
        }
    }

    const float d = dinv[gn];
    float4 bb = bias[lane];
    float4 r;
    r.x = fmaf(d, acc.x, bb.x);
    r.y = fmaf(d, acc.y, bb.y);
    r.z = fmaf(d, acc.z, bb.z);
    r.w = fmaf(d, acc.w, bb.w);
    if (RELU) {
        r.x = fmaxf(r.x, 0.f); r.y = fmaxf(r.y, 0.f);
        r.z = fmaxf(r.z, 0.f); r.w = fmaxf(r.w, 0.f);
    }
    out[(size_t)gn * 16 + lane] = r;
}

// ---------------- launch ----------------
extern "C" void kernel_launch(void* const* d_in, const int* in_sizes, int n_in,
                              void* d_out, int out_size)
{
    const float* x  = (const float*)d_in[0];           // [N, 256]
    const int*   ei = (const int*)  d_in[1];           // [2, E]
    const float* W1 = (const float*)d_in[2];           // [256, 128]
    const float* b1 = (const float*)d_in[3];           // [128]
    const float* W2 = (const float*)d_in[4];           // [128, 64]
    const float* b2 = (const float*)d_in[5];           // [64]
    float* out = (float*)d_out;                        // [N, 64]

    int *degi, *cur, *rowptr, *csr;
    float *dinv, *g1, *h, *g2;
    cudaGetSymbolAddress((void**)&degi,   g_degi);
    cudaGetSymbolAddress((void**)&cur,    g_cur);
    cudaGetSymbolAddress((void**)&rowptr, g_rowptr);
    cudaGetSymbolAddress((void**)&csr,    g_csr);
    cudaGetSymbolAddress((void**)&dinv,   g_dinv);
    cudaGetSymbolAddress((void**)&g1,     g_g1);
    cudaGetSymbolAddress((void**)&h,      g_h);
    cudaGetSymbolAddress((void**)&g2,     g_g2);

    const int T = 256;

    // ---- degree + dinv + CSR build (reused by both layers) ----
    zero_i<<<(N_NODES + T - 1) / T, T>>>(degi, N_NODES);
    zero_i<<<(N_NODES + T - 1) / T, T>>>(cur,  N_NODES);
    deg_accum<<<(N_EDGES + T - 1) / T, T>>>(ei + N_EDGES, degi);
    dinv_kernel<<<(N_NODES + T - 1) / T, T>>>(degi, dinv);
    scan_kernel<<<1, 1024>>>(degi, rowptr);
    csr_fill<<<(N_EDGES + T - 1) / T, T>>>(ei, rowptr, cur, csr);

    // ---- layer 1: g1 = dinv*(x@W1); h = relu(dinv*(Σ g1[nbr] + g1[self]) + b1) ----
    gemm_scale<INDIM, HIDIM, 8, 8>
        <<<(N_NODES + 127) / 128, 256>>>(x, W1, dinv, g1, N_NODES);
    aggregate128<true><<<N_NODES / 8, 256>>>(          // 50000/8 = 6250 exact
        rowptr, csr, (const float4*)g1, dinv, (const float4*)b1, (float4*)h);

    // ---- layer 2 ----
    gemm_scale<HIDIM, OUTDIM, 8, 4>
        <<<(N_NODES + 127) / 128, 256>>>(h, W2, dinv, g2, N_NODES);
    aggregate64<false><<<N_NODES / 16, 256>>>(         // 50000/16 = 3125 exact
        rowptr, csr, (const float4*)g2, dinv, (const float4*)b2, (float4*)out);
}

// round 3
// speedup vs baseline: 1.9180x; 1.3609x over previous
#include <cuda_runtime.h>
#include <cstddef>

#define N_NODES 50000
#define N_EDGES 1600000
#define INDIM   256
#define HIDIM   128
#define OUTDIM  64
#define NB_SCAN ((N_NODES + 255) / 256)   // 196

// ---------------- scratch (allocation-free: __device__ globals) ----------------
__device__ int   g_degi  [N_NODES];
__device__ int   g_cur   [N_NODES];
__device__ int   g_rowptr[N_NODES + 1];
__device__ int   g_csr   [N_EDGES];
__device__ int   g_bsum  [NB_SCAN + 1];
__device__ float g_dinv  [N_NODES];
__device__ float g_u1    [(size_t)N_NODES * HIDIM];   // x @ W1 (raw)
__device__ float g_h     [(size_t)N_NODES * HIDIM];   // layer1 out
__device__ float g_u2    [(size_t)N_NODES * OUTDIM];  // h @ W2 (raw)

// ---------------- f32x2 packed helpers ----------------
__device__ __forceinline__ unsigned long long pk2(float x) {
    unsigned long long r;
    asm("mov.b64 %0, {%1, %1};" : "=l"(r) : "f"(x));
    return r;
}
__device__ __forceinline__ unsigned long long ffma2(unsigned long long a,
                                                    unsigned long long b,
                                                    unsigned long long c) {
    unsigned long long d;
    asm("fma.rn.f32x2 %0, %1, %2, %3;" : "=l"(d) : "l"(a), "l"(b), "l"(c));
    return d;
}

// ---------------- CSR build kernels ----------------
__global__ void zero2_i(int* a, int* b, int n) {
    int i = blockIdx.x * blockDim.x + threadIdx.x;
    if (i < n) { a[i] = 0; b[i] = 0; }
}

__global__ void deg_accum(const int* __restrict__ col, int* __restrict__ degi) {
    int e = blockIdx.x * blockDim.x + threadIdx.x;
    if (e < N_EDGES) atomicAdd(&degi[col[e]], 1);
}

__global__ void dinv_kernel(const int* __restrict__ degi, float* __restrict__ dinv) {
    int i = blockIdx.x * blockDim.x + threadIdx.x;
    if (i < N_NODES) dinv[i] = rsqrtf((float)degi[i] + 1.0f);   // +1 self loop
}

// phase 1: per-block sums of degi (256 elems per block)
__global__ void block_sums(const int* __restrict__ degi, int* __restrict__ bsum) {
    __shared__ int sh[256];
    const int t = threadIdx.x;
    const int i = blockIdx.x * 256 + t;
    sh[t] = (i < N_NODES) ? degi[i] : 0;
    __syncthreads();
    #pragma unroll
    for (int s = 128; s > 0; s >>= 1) {
        if (t < s) sh[t] += sh[t + s];
        __syncthreads();
    }
    if (t == 0) bsum[blockIdx.x] = sh[0];
}

// phase 2: exclusive scan of block sums (single block, 256 >= NB_SCAN)
__global__ void scan_bsums(int* __restrict__ bsum) {
    __shared__ int sh[256];
    const int t = threadIdx.x;
    int v = (t < NB_SCAN) ? bsum[t] : 0;
    sh[t] = v;
    __syncthreads();
    #pragma unroll
    for (int off = 1; off < 256; off <<= 1) {
        int x = (t >= off) ? sh[t - off] : 0;
        __syncthreads();
        sh[t] += x;
        __syncthreads();
    }
    if (t < NB_SCAN) bsum[t] = sh[t] - v;        // exclusive
    if (t == 255)    bsum[NB_SCAN] = sh[255];    // total
}

// phase 3: local exclusive scan + block offset -> rowptr (incl rowptr[N])
__global__ void write_rowptr(const int* __restrict__ degi, const int* __restrict__ bsum,
                             int* __restrict__ rowptr) {
    __shared__ int sh[256];
    const int t = threadIdx.x;
    const int i = blockIdx.x * 256 + t;
    int v = (i < N_NODES) ? degi[i] : 0;
    sh[t] = v;
    __syncthreads();
    #pragma unroll
    for (int off = 1; off < 256; off <<= 1) {
        int x = (t >= off) ? sh[t - off] : 0;
        __syncthreads();
        sh[t] += x;
        __syncthreads();
    }
    if (i <= N_NODES) rowptr[i] = (sh[t] - v) + bsum[blockIdx.x];
}

__global__ void csr_fill(const int* __restrict__ ei, const int* __restrict__ rowptr,
                         int* __restrict__ cur, int* __restrict__ csr) {
    int e = blockIdx.x * blockDim.x + threadIdx.x;
    if (e >= N_EDGES) return;
    int row = ei[e];
    int col = ei[(size_t)N_EDGES + e];
    int pos = rowptr[col] + atomicAdd(&cur[col], 1);
    csr[pos] = row;
}

// ---------------- raw fp32 GEMM with packed f32x2 FMA ----------------
// out[r, :] = A[r, :] @ W    A: n x K row-major, W: K x M row-major
template <int K, int M, int TM, int TN>
__global__ void __launch_bounds__(256, 2)
gemm_raw(const float* __restrict__ A, const float* __restrict__ W,
         float* __restrict__ out, int n)
{
    constexpr int BM = 128;
    constexpr int BK = 16;
    constexpr int TX = M / TN;
    constexpr int TY = BM / TM;
    static_assert(TX * TY == 256, "thread count");
    constexpr int NP = TN / 2;   // packed pairs along N

    __shared__ float As[BK][BM];  // transposed A tile
    __shared__ float Ws[BK][M];

    const int tid = threadIdx.x;
    const int tx  = tid % TX;
    const int ty  = tid / TX;
    const int rowBase = blockIdx.x * BM;

    unsigned long long acc[TM][NP];
    #pragma unroll
    for (int i = 0; i < TM; i++)
        #pragma unroll
        for (int j = 0; j < NP; j++) acc[i][j] = 0ULL;

    constexpr int AF4 = BM * BK / 4;
    constexpr int WF4 = BK * M  / 4;

    for (int k0 = 0; k0 < K; k0 += BK) {
        #pragma unroll
        for (int i = tid; i < AF4; i += 256) {
            int r  = i / (BK / 4);
            int c4 = i % (BK / 4);
            int gr = rowBase + r;
            float4 v = make_float4(0.f, 0.f, 0.f, 0.f);
            if (gr < n)
                v = *reinterpret_cast<const float4*>(&A[(size_t)gr * K + k0 + c4 * 4]);
            As[c4 * 4 + 0][r] = v.x;
            As[c4 * 4 + 1][r] = v.y;
            As[c4 * 4 + 2][r] = v.z;
            As[c4 * 4 + 3][r] = v.w;
        }
        #pragma unroll
        for (int i = tid; i < WF4; i += 256) {
            int r = i / (M / 4);
            int c = i % (M / 4);
            reinterpret_cast<float4*>(&Ws[r][0])[c] =
                *reinterpret_cast<const float4*>(&W[(size_t)(k0 + r) * M + c * 4]);
        }
        __syncthreads();

        #pragma unroll
        for (int kk = 0; kk < BK; kk++) {
            float a[TM];
            #pragma unroll
            for (int i = 0; i < TM; i += 4)
                *reinterpret_cast<float4*>(&a[i]) =
                    *reinterpret_cast<const float4*>(&As[kk][ty * TM + i]);
            unsigned long long bv[NP];
            const unsigned long long* wp =
                reinterpret_cast<const unsigned long long*>(&Ws[kk][tx * TN]);
            #pragma unroll
            for (int j = 0; j < NP; j++) bv[j] = wp[j];
            #pragma unroll
            for (int i = 0; i < TM; i++) {
                unsigned long long av = pk2(a[i]);
                #pragma unroll
                for (int j = 0; j < NP; j++)
                    acc[i][j] = ffma2(av, bv[j], acc[i][j]);
            }
        }
        __syncthreads();
    }

    #pragma unroll
    for (int i = 0; i < TM; i++) {
        int gr = rowBase + ty * TM + i;
        if (gr < n) {
            #pragma unroll
            for (int jp = 0; jp < NP; jp += 2) {
                float x0, y0, x1, y1;
                asm("mov.b64 {%0, %1}, %2;" : "=f"(x0), "=f"(y0) : "l"(acc[i][jp]));
                asm("mov.b64 {%0, %1}, %2;" : "=f"(x1), "=f"(y1) : "l"(acc[i][jp + 1]));
                float4 v = make_float4(x0, y0, x1, y1);
                *reinterpret_cast<float4*>(&out[(size_t)gr * M + tx * TN + jp * 2]) = v;
            }
        }
    }
}

// ---------------- CSR gather-aggregate with per-neighbor dinv, fused epilogue ----
// out[c] = [relu]( dinv[c] * ( sum_{r in N(c)} dinv[r]*u[r] + dinv[c]*u[c] ) + b )
// L = lanes per node (F/4): 32 for F=128, 16 for F=64.
template <int L, bool RELU>
__global__ void aggregate(const int* __restrict__ rowptr, const int* __restrict__ csr,
                          const float4* __restrict__ G, const float* __restrict__ dinv,
                          const float4* __restrict__ bias, float4* __restrict__ out)
{
    const int node = (blockIdx.x * blockDim.x + threadIdx.x) / L;
    const int lane = threadIdx.x % L;

    const float ds = dinv[node];
    float4 acc = G[(size_t)node * L + lane];
    acc.x *= ds; acc.y *= ds; acc.z *= ds; acc.w *= ds;   // self-loop: dinv[c]*u[c]

    const int start = rowptr[node];
    const int end   = rowptr[node + 1];

    int idx = 0; float dd = 0.f;
    if (start + lane < end) { int t = csr[start + lane]; idx = t; dd = dinv[t]; }

    for (int p = start; p < end; p += L) {
        const int m = min(L, end - p);
        // prefetch next batch of indices + weights
        int nidx = 0; float ndd = 0.f;
        if (p + L + lane < end) { int t = csr[p + L + lane]; nidx = t; ndd = dinv[t]; }

        int j = 0;
        for (; j + 4 <= m; j += 4) {
            int   r0 = __shfl_sync(0xffffffffu, idx, j + 0, L);
            int   r1 = __shfl_sync(0xffffffffu, idx, j + 1, L);
            int   r2 = __shfl_sync(0xffffffffu, idx, j + 2, L);
            int   r3 = __shfl_sync(0xffffffffu, idx, j + 3, L);
            float w0 = __shfl_sync(0xffffffffu, dd,  j + 0, L);
            float w1 = __shfl_sync(0xffffffffu, dd,  j + 1, L);
            float w2 = __shfl_sync(0xffffffffu, dd,  j + 2, L);
            float w3 = __shfl_sync(0xffffffffu, dd,  j + 3, L);
            float4 v0 = G[(size_t)r0 * L + lane];
            float4 v1 = G[(size_t)r1 * L + lane];
            float4 v2 = G[(size_t)r2 * L + lane];
            float4 v3 = G[(size_t)r3 * L + lane];
            acc.x = fmaf(w0, v0.x, acc.x); acc.y = fmaf(w0, v0.y, acc.y);
            acc.z = fmaf(w0, v0.z, acc.z); acc.w = fmaf(w0, v0.w, acc.w);
            acc.x = fmaf(w1, v1.x, acc.x); acc.y = fmaf(w1, v1.y, acc.y);
            acc.z = fmaf(w1, v1.z, acc.z); acc.w = fmaf(w1, v1.w, acc.w);
            acc.x = fmaf(w2, v2.x, acc.x); acc.y = fmaf(w2, v2.y, acc.y);
            acc.z = fmaf(w2, v2.z, acc.z); acc.w = fmaf(w2, v2.w, acc.w);
            acc.x = fmaf(w3, v3.x, acc.x); acc.y = fmaf(w3, v3.y, acc.y);
            acc.z = fmaf(w3, v3.z, acc.z); acc.w = fmaf(w3, v3.w, acc.w);
        }
        for (; j < m; j++) {
            int   r = __shfl_sync(0xffffffffu, idx, j, L);
            float w = __shfl_sync(0xffffffffu, dd,  j, L);
            float4 v = G[(size_t)r * L + lane];
            acc.x = fmaf(w, v.x, acc.x); acc.y = fmaf(w, v.y, acc.y);
            acc.z = fmaf(w, v.z, acc.z); acc.w = fmaf(w, v.w, acc.w);
        }
        idx = nidx; dd = ndd;
    }

    float4 bb = bias[lane];
    float4 r;
    r.x = fmaf(ds, acc.x, bb.x);
    r.y = fmaf(ds, acc.y, bb.y);
    r.z = fmaf(ds, acc.z, bb.z);
    r.w = fmaf(ds, acc.w, bb.w);
    if (RELU) {
        r.x = fmaxf(r.x, 0.f); r.y = fmaxf(r.y, 0.f);
        r.z = fmaxf(r.z, 0.f); r.w = fmaxf(r.w, 0.f);
    }
    out[(size_t)node * L + lane] = r;
}

// ---------------- launch ----------------
extern "C" void kernel_launch(void* const* d_in, const int* in_sizes, int n_in,
                              void* d_out, int out_size)
{
    const float* x  = (const float*)d_in[0];           // [N, 256]
    const int*   ei = (const int*)  d_in[1];           // [2, E]
    const float* W1 = (const float*)d_in[2];           // [256, 128]
    const float* b1 = (const float*)d_in[3];           // [128]
    const float* W2 = (const float*)d_in[4];           // [128, 64]
    const float* b2 = (const float*)d_in[5];           // [64]
    float* out = (float*)d_out;                        // [N, 64]

    int *degi, *cur, *rowptr, *csr, *bsum;
    float *dinv, *u1, *h, *u2;
    cudaGetSymbolAddress((void**)&degi,   g_degi);
    cudaGetSymbolAddress((void**)&cur,    g_cur);
    cudaGetSymbolAddress((void**)&rowptr, g_rowptr);
    cudaGetSymbolAddress((void**)&csr,    g_csr);
    cudaGetSymbolAddress((void**)&bsum,   g_bsum);
    cudaGetSymbolAddress((void**)&dinv,   g_dinv);
    cudaGetSymbolAddress((void**)&u1,     g_u1);
    cudaGetSymbolAddress((void**)&h,      g_h);
    cudaGetSymbolAddress((void**)&u2,     g_u2);

    // lazy one-time stream/event setup (first call is the uncaptured
    // correctness run; capture replays the recorded fork/join)
    static cudaStream_t s1 = nullptr;
    static cudaEvent_t  evFork = nullptr, evJoin = nullptr;
    if (!s1) {
        cudaStreamCreateWithFlags(&s1, cudaStreamNonBlocking);
        cudaEventCreateWithFlags(&evFork, cudaEventDisableTiming);
        cudaEventCreateWithFlags(&evJoin, cudaEventDisableTiming);
    }

    const int T = 256;

    // ---- fork: CSR build chain on s1, GEMM1 on main stream ----
    cudaEventRecord(evFork, 0);
    cudaStreamWaitEvent(s1, evFork, 0);

    zero2_i   <<<(N_NODES + T - 1) / T, T, 0, s1>>>(degi, cur, N_NODES);
    deg_accum <<<(N_EDGES + T - 1) / T, T, 0, s1>>>(ei + N_EDGES, degi);
    dinv_kernel<<<(N_NODES + T - 1) / T, T, 0, s1>>>(degi, dinv);
    block_sums<<<NB_SCAN, 256, 0, s1>>>(degi, bsum);
    scan_bsums<<<1, 256, 0, s1>>>(bsum);
    write_rowptr<<<NB_SCAN, 256, 0, s1>>>(degi, bsum, rowptr);
    csr_fill  <<<(N_EDGES + T - 1) / T, T, 0, s1>>>(ei, rowptr, cur, csr);

    // main stream: u1 = x @ W1 (raw, no dinv — decoupled from CSR chain)
    gemm_raw<INDIM, HIDIM, 8, 8>
        <<<(N_NODES + 127) / 128, 256>>>(x, W1, u1, N_NODES);

    // ---- join ----
    cudaEventRecord(evJoin, s1);
    cudaStreamWaitEvent(0, evJoin, 0);

    // layer 1 aggregate: h = relu(dinv*(Σ dinv[r]u1[r] + dinv[c]u1[c]) + b1)
    aggregate<32, true><<<N_NODES / 8, 256>>>(     // 6250 blocks exact
        rowptr, csr, (const float4*)u1, dinv, (const float4*)b1, (float4*)h);

    // layer 2
    gemm_raw<HIDIM, OUTDIM, 8, 4>
        <<<(N_NODES + 127) / 128, 256>>>(h, W2, u2, N_NODES);
    aggregate<16, false><<<N_NODES / 16, 256>>>(   // 3125 blocks exact
        rowptr, csr, (const float4*)u2, dinv, (const float4*)b2, (float4*)out);
}

// round 4
// speedup vs baseline: 2.1006x; 1.0952x over previous
#include <cuda_runtime.h>
#include <cuda_fp16.h>
#include <cstddef>

#define N_NODES 50000
#define N_EDGES 1600000
#define INDIM   256
#define HIDIM   128
#define OUTDIM  64
#define NB_SCAN ((N_NODES + 256) / 256)   // 196 blocks covering N_NODES+1 scan elems

// ---------------- scratch (allocation-free: __device__ globals) ----------------
__device__ int    g_degi  [N_NODES];
__device__ int    g_cur   [N_NODES];
__device__ int    g_rowptr[N_NODES + 1];
__device__ int    g_csr   [N_EDGES];
__device__ unsigned long long g_desc[NB_SCAN];   // lookback descriptors
__device__ float  g_dinv  [N_NODES];
__device__ __half g_u1h   [(size_t)N_NODES * HIDIM];   // x @ W1 (fp16)
__device__ float  g_h     [(size_t)N_NODES * HIDIM];   // layer1 out (fp32)
__device__ __half g_u2h   [(size_t)N_NODES * OUTDIM];  // h @ W2 (fp16)

// ---------------- f32x2 packed helpers ----------------
__device__ __forceinline__ unsigned long long pk2(float x) {
    unsigned long long r;
    asm("mov.b64 %0, {%1, %1};" : "=l"(r) : "f"(x));
    return r;
}
__device__ __forceinline__ unsigned long long ffma2(unsigned long long a,
                                                    unsigned long long b,
                                                    unsigned long long c) {
    unsigned long long d;
    asm("fma.rn.f32x2 %0, %1, %2, %3;" : "=l"(d) : "l"(a), "l"(b), "l"(c));
    return d;
}

// ---------------- CSR build kernels ----------------
__global__ void zero3(int* degi, int* cur, unsigned long long* desc) {
    int i = blockIdx.x * blockDim.x + threadIdx.x;
    if (i < N_NODES) { degi[i] = 0; cur[i] = 0; }
    if (i < NB_SCAN) desc[i] = 0ULL;
}

__global__ void deg_accum(const int* __restrict__ col, int* __restrict__ degi) {
    int e = blockIdx.x * blockDim.x + threadIdx.x;
    if (e < N_EDGES) atomicAdd(&degi[col[e]], 1);
}

// single-pass decoupled-lookback exclusive scan of degi -> rowptr[0..N], plus dinv.
// desc[b]: bits[63:32] flag (0=invalid, 1=aggregate, 2=inclusive-prefix), bits[31:0] value.
__global__ void scan_rowptr(const int* __restrict__ degi, float* __restrict__ dinv,
                            int* __restrict__ rowptr,
                            volatile unsigned long long* desc)
{
    __shared__ int sh[256];
    __shared__ int s_off;
    const int b = blockIdx.x, t = threadIdx.x;
    const int i = b * 256 + t;

    int v = (i < N_NODES) ? degi[i] : 0;
    if (i < N_NODES) dinv[i] = rsqrtf((float)v + 1.0f);   // +1 self loop

    sh[t] = v;
    __syncthreads();
    #pragma unroll
    for (int off = 1; off < 256; off <<= 1) {
        int x = (t >= off) ? sh[t - off] : 0;
        __syncthreads();
        sh[t] += x;
        __syncthreads();
    }
    const int incl  = sh[t];
    const int total = sh[255];

    if (t == 0) {
        if (b == 0) {
            desc[0] = (2ULL << 32) | (unsigned)total;
            s_off = 0;
        } else {
            desc[b] = (1ULL << 32) | (unsigned)total;
            int off = 0;
            int j = b - 1;
            while (true) {
                unsigned long long d;
                do { d = desc[j]; } while ((d >> 32) == 0ULL);
                off += (int)(unsigned)d;
                if ((d >> 32) == 2ULL) break;
                j--;
            }
            desc[b] = (2ULL << 32) | (unsigned)(off + total);
            s_off = off;
        }
    }
    __syncthreads();

    if (i <= N_NODES) rowptr[i] = s_off + incl - v;   // exclusive prefix
}

__global__ void csr_fill(const int* __restrict__ ei, const int* __restrict__ rowptr,
                         int* __restrict__ cur, int* __restrict__ csr) {
    int e = blockIdx.x * blockDim.x + threadIdx.x;
    if (e >= N_EDGES) return;
    int row = ei[e];
    int col = ei[(size_t)N_EDGES + e];
    int pos = rowptr[col] + atomicAdd(&cur[col], 1);
    csr[pos] = row;
}

// ---------------- fp32 GEMM (f32x2 FMA) with fp16 output ----------------
// out_h[r, :] = (half) (A[r, :] @ W)   A: n x K row-major, W: K x M row-major
template <int K, int M, int TM, int TN>
__global__ void __launch_bounds__(256, 2)
gemm_h(const float* __restrict__ A, const float* __restrict__ W,
       __half* __restrict__ out, int n)
{
    constexpr int BM = 128;
    constexpr int BK = 16;
    constexpr int TX = M / TN;
    constexpr int TY = BM / TM;
    static_assert(TX * TY == 256, "thread count");
    constexpr int NP = TN / 2;   // packed pairs along N

    __shared__ float As[BK][BM];  // transposed A tile
    __shared__ float Ws[BK][M];

    const int tid = threadIdx.x;
    const int tx  = tid % TX;
    const int ty  = tid / TX;
    const int rowBase = blockIdx.x * BM;

    unsigned long long acc[TM][NP];
    #pragma unroll
    for (int i = 0; i < TM; i++)
        #pragma unroll
        for (int j = 0; j < NP; j++) acc[i][j] = 0ULL;

    constexpr int AF4 = BM * BK / 4;
    constexpr int WF4 = BK * M  / 4;

    for (int k0 = 0; k0 < K; k0 += BK) {
        #pragma unroll
        for (int i = tid; i < AF4; i += 256) {
            int r  = i / (BK / 4);
            int c4 = i % (BK / 4);
            int gr = rowBase + r;
            float4 v = make_float4(0.f, 0.f, 0.f, 0.f);
            if (gr < n)
                v = *reinterpret_cast<const float4*>(&A[(size_t)gr * K + k0 + c4 * 4]);
            As[c4 * 4 + 0][r] = v.x;
            As[c4 * 4 + 1][r] = v.y;
            As[c4 * 4 + 2][r] = v.z;
            As[c4 * 4 + 3][r] = v.w;
        }
        #pragma unroll
        for (int i = tid; i < WF4; i += 256) {
            int r = i / (M / 4);
            int c = i % (M / 4);
            reinterpret_cast<float4*>(&Ws[r][0])[c] =
                *reinterpret_cast<const float4*>(&W[(size_t)(k0 + r) * M + c * 4]);
        }
        __syncthreads();

        #pragma unroll
        for (int kk = 0; kk < BK; kk++) {
            float a[TM];
            #pragma unroll
            for (int i = 0; i < TM; i += 4)
                *reinterpret_cast<float4*>(&a[i]) =
                    *reinterpret_cast<const float4*>(&As[kk][ty * TM + i]);
            unsigned long long bv[NP];
            const unsigned long long* wp =
                reinterpret_cast<const unsigned long long*>(&Ws[kk][tx * TN]);
            #pragma unroll
            for (int j = 0; j < NP; j++) bv[j] = wp[j];
            #pragma unroll
            for (int i = 0; i < TM; i++) {
                unsigned long long av = pk2(a[i]);
                #pragma unroll
                for (int j = 0; j < NP; j++)
                    acc[i][j] = ffma2(av, bv[j], acc[i][j]);
            }
        }
        __syncthreads();
    }

    #pragma unroll
    for (int i = 0; i < TM; i++) {
        int gr = rowBase + ty * TM + i;
        if (gr < n) {
            #pragma unroll
            for (int jp = 0; jp < NP; jp += 2) {
                float x0, y0, x1, y1;
                asm("mov.b64 {%0, %1}, %2;" : "=f"(x0), "=f"(y0) : "l"(acc[i][jp]));
                asm("mov.b64 {%0, %1}, %2;" : "=f"(x1), "=f"(y1) : "l"(acc[i][jp + 1]));
                __half2 h0 = __floats2half2_rn(x0, y0);
                __half2 h1 = __floats2half2_rn(x1, y1);
                uint2 st;
                st.x = *reinterpret_cast<unsigned*>(&h0);
                st.y = *reinterpret_cast<unsigned*>(&h1);
                *reinterpret_cast<uint2*>(&out[(size_t)gr * M + tx * TN + jp * 2]) = st;
            }
        }
    }
}

// ---------------- CSR gather-aggregate over fp16 messages, fp32 accumulate ----
// out[c] = [relu]( dinv[c] * ( sum_{r in N(c)} dinv[r]*u[r] + dinv[c]*u[c] ) + b )
// L lanes per node, each lane owns 4 features (8 B of fp16 per row).
__device__ __forceinline__ void acc_half4(float4& acc, float w, uint2 raw) {
    __half2 p0 = *reinterpret_cast<__half2*>(&raw.x);
    __half2 p1 = *reinterpret_cast<__half2*>(&raw.y);
    float2 f0 = __half22float2(p0);
    float2 f1 = __half22float2(p1);
    acc.x = fmaf(w, f0.x, acc.x);
    acc.y = fmaf(w, f0.y, acc.y);
    acc.z = fmaf(w, f1.x, acc.z);
    acc.w = fmaf(w, f1.y, acc.w);
}

template <int L, bool RELU>
__global__ void aggregate_h(const int* __restrict__ rowptr, const int* __restrict__ csr,
                            const __half* __restrict__ Gh, const float* __restrict__ dinv,
                            const float4* __restrict__ bias, float4* __restrict__ out)
{
    constexpr int RS = L * 4;     // halves per row
    const int node = (blockIdx.x * blockDim.x + threadIdx.x) / L;
    const int lane = threadIdx.x % L;

    const float ds = dinv[node];
    float4 acc = make_float4(0.f, 0.f, 0.f, 0.f);
    {   // self-loop term: dinv[c] * u[c]
        uint2 raw = *reinterpret_cast<const uint2*>(&Gh[(size_t)node * RS + lane * 4]);
        acc_half4(acc, ds, raw);
    }

    const int start = rowptr[node];
    const int end   = rowptr[node + 1];

    int idx = 0; float dd = 0.f;
    if (start + lane < end) { int t = csr[start + lane]; idx = t; dd = dinv[t]; }

    for (int p = start; p < end; p += L) {
        const int m = min(L, end - p);
        // prefetch next batch of indices + weights
        int nidx = 0; float ndd = 0.f;
        if (p + L + lane < end) { int t = csr[p + L + lane]; nidx = t; ndd = dinv[t]; }

        int j = 0;
        for (; j + 4 <= m; j += 4) {
            int   r0 = __shfl_sync(0xffffffffu, idx, j + 0, L);
            int   r1 = __shfl_sync(0xffffffffu, idx, j + 1, L);
            int   r2 = __shfl_sync(0xffffffffu, idx, j + 2, L);
            int   r3 = __shfl_sync(0xffffffffu, idx, j + 3, L);
            float w0 = __shfl_sync(0xffffffffu, dd,  j + 0, L);
            float w1 = __shfl_sync(0xffffffffu, dd,  j + 1, L);
            float w2 = __shfl_sync(0xffffffffu, dd,  j + 2, L);
            float w3 = __shfl_sync(0xffffffffu, dd,  j + 3, L);
            uint2 a = *reinterpret_cast<const uint2*>(&Gh[(size_t)r0 * RS + lane * 4]);
            uint2 b = *reinterpret_cast<const uint2*>(&Gh[(size_t)r1 * RS + lane * 4]);
            uint2 c = *reinterpret_cast<const uint2*>(&Gh[(size_t)r2 * RS + lane * 4]);
            uint2 d = *reinterpret_cast<const uint2*>(&Gh[(size_t)r3 * RS + lane * 4]);
            acc_half4(acc, w0, a);
            acc_half4(acc, w1, b);
            acc_half4(acc, w2, c);
            acc_half4(acc, w3, d);
        }
        for (; j < m; j++) {
            int   r = __shfl_sync(0xffffffffu, idx, j, L);
            float w = __shfl_sync(0xffffffffu, dd,  j, L);
            uint2 a = *reinterpret_cast<const uint2*>(&Gh[(size_t)r * RS + lane * 4]);
            acc_half4(acc, w, a);
        }
        idx = nidx; dd = ndd;
    }

    float4 bb = bias[lane];
    float4 r;
    r.x = fmaf(ds, acc.x, bb.x);
    r.y = fmaf(ds, acc.y, bb.y);
    r.z = fmaf(ds, acc.z, bb.z);
    r.w = fmaf(ds, acc.w, bb.w);
    if (RELU) {
        r.x = fmaxf(r.x, 0.f); r.y = fmaxf(r.y, 0.f);
        r.z = fmaxf(r.z, 0.f); r.w = fmaxf(r.w, 0.f);
    }
    out[(size_t)node * L + lane] = r;
}

// ---------------- launch ----------------
extern "C" void kernel_launch(void* const* d_in, const int* in_sizes, int n_in,
                              void* d_out, int out_size)
{
    const float* x  = (const float*)d_in[0];           // [N, 256]
    const int*   ei = (const int*)  d_in[1];           // [2, E]
    const float* W1 = (const float*)d_in[2];           // [256, 128]
    const float* b1 = (const float*)d_in[3];           // [128]
    const float* W2 = (const float*)d_in[4];           // [128, 64]
    const float* b2 = (const float*)d_in[5];           // [64]
    float* out = (float*)d_out;                        // [N, 64]

    int *degi, *cur, *rowptr, *csr;
    unsigned long long* desc;
    float *dinv, *h;
    __half *u1h, *u2h;
    cudaGetSymbolAddress((void**)&degi,   g_degi);
    cudaGetSymbolAddress((void**)&cur,    g_cur);
    cudaGetSymbolAddress((void**)&rowptr, g_rowptr);
    cudaGetSymbolAddress((void**)&csr,    g_csr);
    cudaGetSymbolAddress((void**)&desc,   g_desc);
    cudaGetSymbolAddress((void**)&dinv,   g_dinv);
    cudaGetSymbolAddress((void**)&u1h,    g_u1h);
    cudaGetSymbolAddress((void**)&h,      g_h);
    cudaGetSymbolAddress((void**)&u2h,    g_u2h);

    // lazy one-time stream/event setup
    static cudaStream_t s1 = nullptr;
    static cudaEvent_t  evFork = nullptr, evJoin = nullptr;
    if (!s1) {
        cudaStreamCreateWithFlags(&s1, cudaStreamNonBlocking);
        cudaEventCreateWithFlags(&evFork, cudaEventDisableTiming);
        cudaEventCreateWithFlags(&evJoin, cudaEventDisableTiming);
    }

    const int T = 256;

    // ---- fork: CSR build chain on s1, GEMM1 on main stream ----
    cudaEventRecord(evFork, 0);
    cudaStreamWaitEvent(s1, evFork, 0);

    zero3      <<<(N_NODES + T - 1) / T, T, 0, s1>>>(degi, cur, desc);       // launch 1
    deg_accum  <<<(N_EDGES + T - 1) / T, T, 0, s1>>>(ei + N_EDGES, degi);    // launch 2
    scan_rowptr<<<NB_SCAN, 256, 0, s1>>>(degi, dinv, rowptr, desc);          // launch 3
    csr_fill   <<<(N_EDGES + T - 1) / T, T, 0, s1>>>(ei, rowptr, cur, csr);  // launch 4

    // main stream: u1h = (half)(x @ W1)
    gemm_h<INDIM, HIDIM, 8, 8>
        <<<(N_NODES + 127) / 128, 256>>>(x, W1, u1h, N_NODES);               // launch 5

    // ---- join ----
    cudaEventRecord(evJoin, s1);
    cudaStreamWaitEvent(0, evJoin, 0);

    // layer 1 aggregate (launch 6 -> ncu -s 5 profiles this)
    aggregate_h<32, true><<<N_NODES / 8, 256>>>(
        rowptr, csr, u1h, dinv, (const float4*)b1, (float4*)h);

    // layer 2
    gemm_h<HIDIM, OUTDIM, 8, 4>
        <<<(N_NODES + 127) / 128, 256>>>(h, W2, u2h, N_NODES);
    aggregate_h<16, false><<<N_NODES / 16, 256>>>(
        rowptr, csr, u2h, dinv, (const float4*)b2, (float4*)out);
}

// round 5
// speedup vs baseline: 2.6911x; 1.2812x over previous
#include <cuda_runtime.h>
#include <cuda_fp16.h>
#include <cstddef>
#include <cstdint>

#define N_NODES 50000
#define N_EDGES 1600000
#define INDIM   256
#define HIDIM   128
#define OUTDIM  64
#define NB_SCAN ((N_NODES + 256) / 256)   // 196

// ---------------- scratch (allocation-free: __device__ globals) ----------------
__device__ int    g_degi  [N_NODES];
__device__ int    g_cur   [N_NODES];
__device__ int    g_rowptr[N_NODES + 1];
__device__ int    g_csr   [N_EDGES];
__device__ unsigned long long g_desc[NB_SCAN];
__device__ float  g_dinv  [N_NODES];
__device__ __half g_xh    [(size_t)N_NODES * INDIM];   // x in fp16
__device__ __half g_wt1   [(size_t)HIDIM * INDIM];     // W1^T fp16 [128][256]
__device__ __half g_wt2   [(size_t)OUTDIM * HIDIM];    // W2^T fp16 [64][128]
__device__ __half g_u1h   [(size_t)N_NODES * HIDIM];   // x @ W1 (fp16)
__device__ __half g_h     [(size_t)N_NODES * HIDIM];   // layer1 out (fp16)
__device__ __half g_u2h   [(size_t)N_NODES * OUTDIM];  // h @ W2 (fp16)

// ---------------- CSR build kernels ----------------
__global__ void zero3(int* degi, int* cur, unsigned long long* desc) {
    int i = blockIdx.x * blockDim.x + threadIdx.x;
    if (i < N_NODES) { degi[i] = 0; cur[i] = 0; }
    if (i < NB_SCAN) desc[i] = 0ULL;
}

__global__ void deg_accum(const int* __restrict__ col, int* __restrict__ degi) {
    int e = blockIdx.x * blockDim.x + threadIdx.x;
    if (e < N_EDGES) atomicAdd(&degi[col[e]], 1);
}

// single-pass decoupled-lookback exclusive scan of degi -> rowptr[0..N], plus dinv.
__global__ void scan_rowptr(const int* __restrict__ degi, float* __restrict__ dinv,
                            int* __restrict__ rowptr,
                            volatile unsigned long long* desc)
{
    __shared__ int sh[256];
    __shared__ int s_off;
    const int b = blockIdx.x, t = threadIdx.x;
    const int i = b * 256 + t;

    int v = (i < N_NODES) ? degi[i] : 0;
    if (i < N_NODES) dinv[i] = rsqrtf((float)v + 1.0f);

    sh[t] = v;
    __syncthreads();
    #pragma unroll
    for (int off = 1; off < 256; off <<= 1) {
        int x = (t >= off) ? sh[t - off] : 0;
        __syncthreads();
        sh[t] += x;
        __syncthreads();
    }
    const int incl  = sh[t];
    const int total = sh[255];

    if (t == 0) {
        if (b == 0) {
            desc[0] = (2ULL << 32) | (unsigned)total;
            s_off = 0;
        } else {
            desc[b] = (1ULL << 32) | (unsigned)total;
            int off = 0;
            int j = b - 1;
            while (true) {
                unsigned long long d;
                do { d = desc[j]; } while ((d >> 32) == 0ULL);
                off += (int)(unsigned)d;
                if ((d >> 32) == 2ULL) break;
                j--;
            }
            desc[b] = (2ULL << 32) | (unsigned)(off + total);
            s_off = off;
        }
    }
    __syncthreads();

    if (i <= N_NODES) rowptr[i] = s_off + incl - v;
}

__global__ void csr_fill(const int* __restrict__ ei, const int* __restrict__ rowptr,
                         int* __restrict__ cur, int* __restrict__ csr) {
    int e = blockIdx.x * blockDim.x + threadIdx.x;
    if (e >= N_EDGES) return;
    int row = ei[e];
    int col = ei[(size_t)N_EDGES + e];
    int pos = rowptr[col] + atomicAdd(&cur[col], 1);
    csr[pos] = row;
}

// ---------------- conversion kernels ----------------
__global__ void conv_x_half(const float4* __restrict__ x, uint2* __restrict__ xh, size_t n4) {
    size_t i = (size_t)blockIdx.x * blockDim.x + threadIdx.x;
    if (i >= n4) return;
    float4 v = x[i];
    __half2 h0 = __floats2half2_rn(v.x, v.y);
    __half2 h1 = __floats2half2_rn(v.z, v.w);
    uint2 o;
    o.x = *reinterpret_cast<unsigned*>(&h0);
    o.y = *reinterpret_cast<unsigned*>(&h1);
    xh[i] = o;
}

// W [K][M] fp32 -> Wt [M][K] fp16
__global__ void conv_wt(const float* __restrict__ W, __half* __restrict__ Wt, int K, int M) {
    int o = blockIdx.x * blockDim.x + threadIdx.x;
    if (o >= K * M) return;
    int m = o / K, k = o % K;
    Wt[o] = __float2half(W[(size_t)k * M + m]);
}

// ---------------- tensor-core fp16 GEMM: out = A @ Bt^T ----------------
// A [n][K] fp16 row-major, Bt [BN][K] fp16 (= W^T), out [n][BN] fp16.
// mma.sync.m16n8k16 f32 accum. Block 128 x BN, 8 warps (4x2), warp 32 x BN/2.
__device__ __forceinline__ void mma16816(float* c, const unsigned* a,
                                         unsigned b0, unsigned b1) {
    asm volatile(
        "mma.sync.aligned.m16n8k16.row.col.f32.f16.f16.f32 "
        "{%0,%1,%2,%3}, {%4,%5,%6,%7}, {%8,%9}, {%0,%1,%2,%3};"
        : "+f"(c[0]), "+f"(c[1]), "+f"(c[2]), "+f"(c[3])
        : "r"(a[0]), "r"(a[1]), "r"(a[2]), "r"(a[3]), "r"(b0), "r"(b1));
}

template <int K, int BN>
__global__ void __launch_bounds__(256)
gemm_mma(const __half* __restrict__ A, const __half* __restrict__ Bt,
         __half* __restrict__ out, int n)
{
    constexpr int BM  = 128;
    constexpr int BK  = 32;
    constexpr int PAD = 40;               // padded halves per smem row
    constexpr int WN  = BN / 2;           // warp n extent
    constexpr int NT  = WN / 8;           // n-tiles per warp
    constexpr int AL  = (BM * 8) / 256;   // uint2 loads per thread (A)
    constexpr int BL  = (BN * 8) / 256;   // uint2 loads per thread (B)

    __shared__ __half As[2][BM][PAD];
    __shared__ __half Bs[2][BN][PAD];

    const int tid  = threadIdx.x;
    const int lane = tid & 31;
    const int wid  = tid >> 5;
    const int wr   = wid & 3;             // warp row 0..3
    const int wc   = wid >> 2;            // warp col 0..1
    const int rowBase = blockIdx.x * BM;

    const int r4 = lane >> 2;             // 0..7
    const int c2 = (lane & 3) * 2;        // 0,2,4,6

    float acc[2][NT][4];
    #pragma unroll
    for (int mt = 0; mt < 2; mt++)
        #pragma unroll
        for (int nt = 0; nt < NT; nt++)
            #pragma unroll
            for (int q = 0; q < 4; q++) acc[mt][nt][q] = 0.f;

    uint2 abuf[AL], bbuf[BL];

    auto loadA = [&](int k0) {
        #pragma unroll
        for (int i = 0; i < AL; i++) {
            int idx = tid + i * 256;
            int r = idx >> 3, sg = idx & 7;
            int gr = rowBase + r;
            uint2 v = make_uint2(0u, 0u);
            if (gr < n)
                v = *reinterpret_cast<const uint2*>(&A[(size_t)gr * K + k0 + sg * 4]);
            abuf[i] = v;
        }
    };
    auto loadB = [&](int k0) {
        #pragma unroll
        for (int i = 0; i < BL; i++) {
            int idx = tid + i * 256;
            int r = idx >> 3, sg = idx & 7;
            bbuf[i] = *reinterpret_cast<const uint2*>(&Bt[(size_t)r * K + k0 + sg * 4]);
        }
    };
    auto store = [&](int s) {
        #pragma unroll
        for (int i = 0; i < AL; i++) {
            int idx = tid + i * 256;
            int r = idx >> 3, sg = idx & 7;
            *reinterpret_cast<uint2*>(&As[s][r][sg * 4]) = abuf[i];
        }
        #pragma unroll
        for (int i = 0; i < BL; i++) {
            int idx = tid + i * 256;
            int r = idx >> 3, sg = idx & 7;
            *reinterpret_cast<uint2*>(&Bs[s][r][sg * 4]) = bbuf[i];
        }
    };

    loadA(0); loadB(0);
    store(0);
    __syncthreads();

    constexpr int NSTEP = K / BK;
    #pragma unroll
    for (int step = 0; step < NSTEP; step++) {
        const int s = step & 1;
        if (step + 1 < NSTEP) { loadA((step + 1) * BK); loadB((step + 1) * BK); }

        #pragma unroll
        for (int ks = 0; ks < BK; ks += 16) {
            unsigned a[2][4];
            #pragma unroll
            for (int mt = 0; mt < 2; mt++) {
                int m0 = wr * 32 + mt * 16;
                a[mt][0] = *reinterpret_cast<const unsigned*>(&As[s][m0 + r4    ][ks + c2    ]);
                a[mt][1] = *reinterpret_cast<const unsigned*>(&As[s][m0 + r4 + 8][ks + c2    ]);
                a[mt][2] = *reinterpret_cast<const unsigned*>(&As[s][m0 + r4    ][ks + c2 + 8]);
                a[mt][3] = *reinterpret_cast<const unsigned*>(&As[s][m0 + r4 + 8][ks + c2 + 8]);
            }
            #pragma unroll
            for (int nt = 0; nt < NT; nt++) {
                int n0 = wc * WN + nt * 8;
                unsigned b0 = *reinterpret_cast<const unsigned*>(&Bs[s][n0 + r4][ks + c2    ]);
                unsigned b1 = *reinterpret_cast<const unsigned*>(&Bs[s][n0 + r4][ks + c2 + 8]);
                mma16816(acc[0][nt], a[0], b0, b1);
                mma16816(acc[1][nt], a[1], b0, b1);
            }
        }
        __syncthreads();
        if (step + 1 < NSTEP) {
            store(s ^ 1);
            __syncthreads();
        }
    }

    // epilogue: fp16 store
    #pragma unroll
    for (int mt = 0; mt < 2; mt++) {
        #pragma unroll
        for (int nt = 0; nt < NT; nt++) {
            int row0 = rowBase + wr * 32 + mt * 16 + r4;
            int col  = wc * WN + nt * 8 + c2;
            if (row0 < n) {
                __half2 h = __floats2half2_rn(acc[mt][nt][0], acc[mt][nt][1]);
                *reinterpret_cast<unsigned*>(&out[(size_t)row0 * BN + col]) =
                    *reinterpret_cast<unsigned*>(&h);
            }
            if (row0 + 8 < n) {
                __half2 h = __floats2half2_rn(acc[mt][nt][2], acc[mt][nt][3]);
                *reinterpret_cast<unsigned*>(&out[(size_t)(row0 + 8) * BN + col]) =
                    *reinterpret_cast<unsigned*>(&h);
            }
        }
    }
}

// ---------------- CSR gather-aggregate over fp16 messages ----------------
__device__ __forceinline__ void acc_half4(float4& acc, float w, uint2 raw) {
    __half2 p0 = *reinterpret_cast<__half2*>(&raw.x);
    __half2 p1 = *reinterpret_cast<__half2*>(&raw.y);
    float2 f0 = __half22float2(p0);
    float2 f1 = __half22float2(p1);
    acc.x = fmaf(w, f0.x, acc.x);
    acc.y = fmaf(w, f0.y, acc.y);
    acc.z = fmaf(w, f1.x, acc.z);
    acc.w = fmaf(w, f1.y, acc.w);
}

// out[c] = [relu]( dinv[c] * ( sum_{r in N(c)} dinv[r]*u[r] + dinv[c]*u[c] ) + b )
// HOUT: write fp16 (uint2 per lane) else fp32 (float4 per lane).
template <int L, bool RELU, bool HOUT>
__global__ void aggregate_h(const int* __restrict__ rowptr, const int* __restrict__ csr,
                            const __half* __restrict__ Gh, const float* __restrict__ dinv,
                            const float4* __restrict__ bias, void* __restrict__ outv)
{
    constexpr int RS = L * 4;     // halves per row
    const int node = (blockIdx.x * blockDim.x + threadIdx.x) / L;
    const int lane = threadIdx.x % L;

    const float ds = dinv[node];
    float4 acc = make_float4(0.f, 0.f, 0.f, 0.f);
    {
        uint2 raw = *reinterpret_cast<const uint2*>(&Gh[(size_t)node * RS + lane * 4]);
        acc_half4(acc, ds, raw);
    }

    const int start = rowptr[node];
    const int end   = rowptr[node + 1];

    int idx = 0; float dd = 0.f;
    if (start + lane < end) { int t = csr[start + lane]; idx = t; dd = dinv[t]; }

    for (int p = start; p < end; p += L) {
        const int m = min(L, end - p);
        int nidx = 0; float ndd = 0.f;
        if (p + L + lane < end) { int t = csr[p + L + lane]; nidx = t; ndd = dinv[t]; }

        int j = 0;
        for (; j + 4 <= m; j += 4) {
            int   r0 = __shfl_sync(0xffffffffu, idx, j + 0, L);
            int   r1 = __shfl_sync(0xffffffffu, idx, j + 1, L);
            int   r2 = __shfl_sync(0xffffffffu, idx, j + 2, L);
            int   r3 = __shfl_sync(0xffffffffu, idx, j + 3, L);
            float w0 = __shfl_sync(0xffffffffu, dd,  j + 0, L);
            float w1 = __shfl_sync(0xffffffffu, dd,  j + 1, L);
            float w2 = __shfl_sync(0xffffffffu, dd,  j + 2, L);
            float w3 = __shfl_sync(0xffffffffu, dd,  j + 3, L);
            uint2 a = *reinterpret_cast<const uint2*>(&Gh[(size_t)r0 * RS + lane * 4]);
            uint2 b = *reinterpret_cast<const uint2*>(&Gh[(size_t)r1 * RS + lane * 4]);
            uint2 c = *reinterpret_cast<const uint2*>(&Gh[(size_t)r2 * RS + lane * 4]);
            uint2 d = *reinterpret_cast<const uint2*>(&Gh[(size_t)r3 * RS + lane * 4]);
            acc_half4(acc, w0, a);
            acc_half4(acc, w1, b);
            acc_half4(acc, w2, c);
            acc_half4(acc, w3, d);
        }
        for (; j < m; j++) {
            int   r = __shfl_sync(0xffffffffu, idx, j, L);
            float w = __shfl_sync(0xffffffffu, dd,  j, L);
            uint2 a = *reinterpret_cast<const uint2*>(&Gh[(size_t)r * RS + lane * 4]);
            acc_half4(acc, w, a);
        }
        idx = nidx; dd = ndd;
    }

    float4 bb = bias[lane];
    float4 r;
    r.x = fmaf(ds, acc.x, bb.x);
    r.y = fmaf(ds, acc.y, bb.y);
    r.z = fmaf(ds, acc.z, bb.z);
    r.w = fmaf(ds, acc.w, bb.w);
    if (RELU) {
        r.x = fmaxf(r.x, 0.f); r.y = fmaxf(r.y, 0.f);
        r.z = fmaxf(r.z, 0.f); r.w = fmaxf(r.w, 0.f);
    }
    if (HOUT) {
        __half2 h0 = __floats2half2_rn(r.x, r.y);
        __half2 h1 = __floats2half2_rn(r.z, r.w);
        uint2 o;
        o.x = *reinterpret_cast<unsigned*>(&h0);
        o.y = *reinterpret_cast<unsigned*>(&h1);
        reinterpret_cast<uint2*>(outv)[(size_t)node * L + lane] = o;
    } else {
        reinterpret_cast<float4*>(outv)[(size_t)node * L + lane] = r;
    }
}

// ---------------- launch ----------------
extern "C" void kernel_launch(void* const* d_in, const int* in_sizes, int n_in,
                              void* d_out, int out_size)
{
    const float* x  = (const float*)d_in[0];
    const int*   ei = (const int*)  d_in[1];
    const float* W1 = (const float*)d_in[2];
    const float* b1 = (const float*)d_in[3];
    const float* W2 = (const float*)d_in[4];
    const float* b2 = (const float*)d_in[5];
    float* out = (float*)d_out;

    int *degi, *cur, *rowptr, *csr;
    unsigned long long* desc;
    float *dinv;
    __half *xh, *wt1, *wt2, *u1h, *h, *u2h;
    cudaGetSymbolAddress((void**)&degi,   g_degi);
    cudaGetSymbolAddress((void**)&cur,    g_cur);
    cudaGetSymbolAddress((void**)&rowptr, g_rowptr);
    cudaGetSymbolAddress((void**)&csr,    g_csr);
    cudaGetSymbolAddress((void**)&desc,   g_desc);
    cudaGetSymbolAddress((void**)&dinv,   g_dinv);
    cudaGetSymbolAddress((void**)&xh,     g_xh);
    cudaGetSymbolAddress((void**)&wt1,    g_wt1);
    cudaGetSymbolAddress((void**)&wt2,    g_wt2);
    cudaGetSymbolAddress((void**)&u1h,    g_u1h);
    cudaGetSymbolAddress((void**)&h,      g_h);
    cudaGetSymbolAddress((void**)&u2h,    g_u2h);

    static cudaStream_t s1 = nullptr;
    static cudaEvent_t  evFork = nullptr, evJoin = nullptr;
    if (!s1) {
        cudaStreamCreateWithFlags(&s1, cudaStreamNonBlocking);
        cudaEventCreateWithFlags(&evFork, cudaEventDisableTiming);
        cudaEventCreateWithFlags(&evJoin, cudaEventDisableTiming);
    }

    const int T = 256;

    // ---- fork: CSR build chain on s1 ----
    cudaEventRecord(evFork, 0);
    cudaStreamWaitEvent(s1, evFork, 0);

    zero3      <<<(N_NODES + T - 1) / T, T, 0, s1>>>(degi, cur, desc);
    deg_accum  <<<(N_EDGES + T - 1) / T, T, 0, s1>>>(ei + N_EDGES, degi);
    scan_rowptr<<<NB_SCAN, 256, 0, s1>>>(degi, dinv, rowptr, desc);
    csr_fill   <<<(N_EDGES + T - 1) / T, T, 0, s1>>>(ei, rowptr, cur, csr);

    // ---- main stream: conversions + GEMM1 ----
    {
        size_t n4 = (size_t)N_NODES * INDIM / 4;
        conv_x_half<<<(int)((n4 + T - 1) / T), T>>>((const float4*)x, (uint2*)xh, n4);
    }
    conv_wt<<<(INDIM * HIDIM + T - 1) / T, T>>>(W1, wt1, INDIM, HIDIM);
    conv_wt<<<(HIDIM * OUTDIM + T - 1) / T, T>>>(W2, wt2, HIDIM, OUTDIM);

    gemm_mma<INDIM, HIDIM>
        <<<(N_NODES + 127) / 128, 256>>>(xh, wt1, u1h, N_NODES);

    // ---- join ----
    cudaEventRecord(evJoin, s1);
    cudaStreamWaitEvent(0, evJoin, 0);

    // layer 1 aggregate -> h (fp16)
    aggregate_h<32, true, true><<<N_NODES / 8, 256>>>(
        rowptr, csr, u1h, dinv, (const float4*)b1, (void*)h);

    // layer 2
    gemm_mma<HIDIM, OUTDIM>
        <<<(N_NODES + 127) / 128, 256>>>(h, wt2, u2h, N_NODES);
    aggregate_h<16, false, false><<<N_NODES / 16, 256>>>(
        rowptr, csr, u2h, dinv, (const float4*)b2, (void*)out);
}

// round 6
// speedup vs baseline: 2.8313x; 1.0521x over previous
#include <cuda_runtime.h>
#include <cuda_fp16.h>
#include <cstddef>
#include <cstdint>

#define N_NODES 50000
#define N_EDGES 1600000
#define INDIM   256
#define HIDIM   128
#define OUTDIM  64
#define NB_SCAN ((N_NODES + 256) / 256)   // 196

// ---------------- scratch (allocation-free: __device__ globals) ----------------
__device__ int    g_degi  [N_NODES];
__device__ int    g_cur   [N_NODES];        // running write cursor (init = rowptr)
__device__ int    g_rowptr[N_NODES + 1];
__device__ int    g_csr   [N_EDGES];
__device__ unsigned long long g_desc[NB_SCAN];
__device__ float  g_dinv  [N_NODES];
__device__ __half g_wt1   [(size_t)HIDIM * INDIM];     // W1^T fp16 [128][256]
__device__ __half g_wt2   [(size_t)OUTDIM * HIDIM];    // W2^T fp16 [64][128]
__device__ __half g_u1h   [(size_t)N_NODES * HIDIM];   // x @ W1 (fp16)
__device__ __half g_h     [(size_t)N_NODES * HIDIM];   // layer1 out (fp16)
__device__ __half g_u2h   [(size_t)N_NODES * OUTDIM];  // h @ W2 (fp16)

// ---------------- CSR build kernels ----------------
__global__ void zero2(int* degi, unsigned long long* desc) {
    int i = blockIdx.x * blockDim.x + threadIdx.x;
    if (i < N_NODES) degi[i] = 0;
    if (i < NB_SCAN) desc[i] = 0ULL;
}

// 4 edges per thread, int4 loads (E divisible by 4)
__global__ void deg_accum4(const int4* __restrict__ col4, int* __restrict__ degi) {
    int i = blockIdx.x * blockDim.x + threadIdx.x;
    if (i >= N_EDGES / 4) return;
    int4 c = col4[i];
    atomicAdd(&degi[c.x], 1);
    atomicAdd(&degi[c.y], 1);
    atomicAdd(&degi[c.z], 1);
    atomicAdd(&degi[c.w], 1);
}

// single-pass scan with PARALLEL lookback (all 196 blocks co-resident).
// Also writes dinv and initializes cur = rowptr.
__global__ void scan_rowptr(const int* __restrict__ degi, float* __restrict__ dinv,
                            int* __restrict__ rowptr, int* __restrict__ cur,
                            volatile unsigned long long* desc)
{
    __shared__ int sh[256];
    __shared__ int red[256];
    const int b = blockIdx.x, t = threadIdx.x;
    const int i = b * 256 + t;

    int v = (i < N_NODES) ? degi[i] : 0;
    if (i < N_NODES) dinv[i] = rsqrtf((float)v + 1.0f);   // +1 self loop

    sh[t] = v;
    __syncthreads();
    #pragma unroll
    for (int off = 1; off < 256; off <<= 1) {
        int x = (t >= off) ? sh[t - off] : 0;
        __syncthreads();
        sh[t] += x;
        __syncthreads();
    }
    const int incl  = sh[t];
    const int total = sh[255];

    // publish this block's aggregate (value packaged with nonzero flag)
    if (t == 0) desc[b] = (1ULL << 32) | (unsigned)total;

    // parallel lookback: thread t (< b) spins on predecessor t's descriptor
    int contrib = 0;
    if (t < b) {
        unsigned long long d;
        do { d = desc[t]; } while ((d >> 32) == 0ULL);
        contrib = (int)(unsigned)d;
    }
    red[t] = contrib;
    __syncthreads();
    #pragma unroll
    for (int s = 128; s > 0; s >>= 1) {
        if (t < s) red[t] += red[t + s];
        __syncthreads();
    }
    const int off = red[0];

    if (i <= N_NODES) {
        int rp = off + incl - v;    // exclusive prefix
        rowptr[i] = rp;
        if (i < N_NODES) cur[i] = rp;
    }
}

// 4 edges per thread; cur pre-initialized to rowptr, so no rowptr gather.
__global__ void csr_fill4(const int4* __restrict__ row4, const int4* __restrict__ col4,
                          int* __restrict__ cur, int* __restrict__ csr) {
    int i = blockIdx.x * blockDim.x + threadIdx.x;
    if (i >= N_EDGES / 4) return;
    int4 r = row4[i];
    int4 c = col4[i];
    int p0 = atomicAdd(&cur[c.x], 1);
    int p1 = atomicAdd(&cur[c.y], 1);
    int p2 = atomicAdd(&cur[c.z], 1);
    int p3 = atomicAdd(&cur[c.w], 1);
    csr[p0] = r.x;
    csr[p1] = r.y;
    csr[p2] = r.z;
    csr[p3] = r.w;
}

// ---------------- weight transpose/convert: W [K][M] fp32 -> Wt [M][K] fp16 ----
__global__ void conv_wt(const float* __restrict__ W, __half* __restrict__ Wt, int K, int M) {
    int o = blockIdx.x * blockDim.x + threadIdx.x;
    if (o >= K * M) return;
    int m = o / K, k = o % K;
    Wt[o] = __float2half(W[(size_t)k * M + m]);
}

// ---------------- tensor-core fp16 GEMM: out = A @ Bt^T ----------------
// A [n][K] row-major (fp32 if AF32, converted on tile load; else fp16),
// Bt [BN][K] fp16 (= W^T), out [n][BN] fp16.
__device__ __forceinline__ void mma16816(float* c, const unsigned* a,
                                         unsigned b0, unsigned b1) {
    asm volatile(
        "mma.sync.aligned.m16n8k16.row.col.f32.f16.f16.f32 "
        "{%0,%1,%2,%3}, {%4,%5,%6,%7}, {%8,%9}, {%0,%1,%2,%3};"
        : "+f"(c[0]), "+f"(c[1]), "+f"(c[2]), "+f"(c[3])
        : "r"(a[0]), "r"(a[1]), "r"(a[2]), "r"(a[3]), "r"(b0), "r"(b1));
}

template <int K, int BN, bool AF32>
__global__ void __launch_bounds__(256)
gemm_mma(const void* __restrict__ Av, const __half* __restrict__ Bt,
         __half* __restrict__ out, int n)
{
    constexpr int BM  = 128;
    constexpr int BK  = 32;
    constexpr int PAD = 40;
    constexpr int WN  = BN / 2;
    constexpr int NT  = WN / 8;
    constexpr int AL  = (BM * 8) / 256;   // uint2(4-half) chunks per thread (A)
    constexpr int BL  = (BN * 8) / 256;

    __shared__ __half As[2][BM][PAD];
    __shared__ __half Bs[2][BN][PAD];

    const int tid  = threadIdx.x;
    const int lane = tid & 31;
    const int wid  = tid >> 5;
    const int wr   = wid & 3;
    const int wc   = wid >> 2;
    const int rowBase = blockIdx.x * BM;

    const int r4 = lane >> 2;
    const int c2 = (lane & 3) * 2;

    float acc[2][NT][4];
    #pragma unroll
    for (int mt = 0; mt < 2; mt++)
        #pragma unroll
        for (int nt = 0; nt < NT; nt++)
            #pragma unroll
            for (int q = 0; q < 4; q++) acc[mt][nt][q] = 0.f;

    uint2 abuf[AL], bbuf[BL];

    auto loadA = [&](int k0) {
        #pragma unroll
        for (int i = 0; i < AL; i++) {
            int idx = tid + i * 256;
            int r = idx >> 3, sg = idx & 7;
            int gr = rowBase + r;
            uint2 v = make_uint2(0u, 0u);
            if (gr < n) {
                if (AF32) {
                    float4 f = *reinterpret_cast<const float4*>(
                        (const float*)Av + (size_t)gr * K + k0 + sg * 4);
                    __half2 h0 = __floats2half2_rn(f.x, f.y);
                    __half2 h1 = __floats2half2_rn(f.z, f.w);
                    v.x = *reinterpret_cast<unsigned*>(&h0);
                    v.y = *reinterpret_cast<unsigned*>(&h1);
                } else {
                    v = *reinterpret_cast<const uint2*>(
                        (const __half*)Av + (size_t)gr * K + k0 + sg * 4);
                }
            }
            abuf[i] = v;
        }
    };
    auto loadB = [&](int k0) {
        #pragma unroll
        for (int i = 0; i < BL; i++) {
            int idx = tid + i * 256;
            int r = idx >> 3, sg = idx & 7;
            bbuf[i] = *reinterpret_cast<const uint2*>(&Bt[(size_t)r * K + k0 + sg * 4]);
        }
    };
    auto store = [&](int s) {
        #pragma unroll
        for (int i = 0; i < AL; i++) {
            int idx = tid + i * 256;
            int r = idx >> 3, sg = idx & 7;
            *reinterpret_cast<uint2*>(&As[s][r][sg * 4]) = abuf[i];
        }
        #pragma unroll
        for (int i = 0; i < BL; i++) {
            int idx = tid + i * 256;
            int r = idx >> 3, sg = idx & 7;
            *reinterpret_cast<uint2*>(&Bs[s][r][sg * 4]) = bbuf[i];
        }
    };

    loadA(0); loadB(0);
    store(0);
    __syncthreads();

    constexpr int NSTEP = K / BK;
    #pragma unroll
    for (int step = 0; step < NSTEP; step++) {
        const int s = step & 1;
        if (step + 1 < NSTEP) { loadA((step + 1) * BK); loadB((step + 1) * BK); }

        #pragma unroll
        for (int ks = 0; ks < BK; ks += 16) {
            unsigned a[2][4];
            #pragma unroll
            for (int mt = 0; mt < 2; mt++) {
                int m0 = wr * 32 + mt * 16;
                a[mt][0] = *reinterpret_cast<const unsigned*>(&As[s][m0 + r4    ][ks + c2    ]);
                a[mt][1] = *reinterpret_cast<const unsigned*>(&As[s][m0 + r4 + 8][ks + c2    ]);
                a[mt][2] = *reinterpret_cast<const unsigned*>(&As[s][m0 + r4    ][ks + c2 + 8]);
                a[mt][3] = *reinterpret_cast<const unsigned*>(&As[s][m0 + r4 + 8][ks + c2 + 8]);
            }
            #pragma unroll
            for (int nt = 0; nt < NT; nt++) {
                int n0 = wc * WN + nt * 8;
                unsigned b0 = *reinterpret_cast<const unsigned*>(&Bs[s][n0 + r4][ks + c2    ]);
                unsigned b1 = *reinterpret_cast<const unsigned*>(&Bs[s][n0 + r4][ks + c2 + 8]);
                mma16816(acc[0][nt], a[0], b0, b1);
                mma16816(acc[1][nt], a[1], b0, b1);
            }
        }
        __syncthreads();
        if (step + 1 < NSTEP) {
            store(s ^ 1);
            __syncthreads();
        }
    }

    #pragma unroll
    for (int mt = 0; mt < 2; mt++) {
        #pragma unroll
        for (int nt = 0; nt < NT; nt++) {
            int row0 = rowBase + wr * 32 + mt * 16 + r4;
            int col  = wc * WN + nt * 8 + c2;
            if (row0 < n) {
                __half2 h = __floats2half2_rn(acc[mt][nt][0], acc[mt][nt][1]);
                *reinterpret_cast<unsigned*>(&out[(size_t)row0 * BN + col]) =
                    *reinterpret_cast<unsigned*>(&h);
            }
            if (row0 + 8 < n) {
                __half2 h = __floats2half2_rn(acc[mt][nt][2], acc[mt][nt][3]);
                *reinterpret_cast<unsigned*>(&out[(size_t)(row0 + 8) * BN + col]) =
                    *reinterpret_cast<unsigned*>(&h);
            }
        }
    }
}

// ---------------- CSR gather-aggregate over fp16 messages ----------------
__device__ __forceinline__ void acc_half4(float4& acc, float w, uint2 raw) {
    __half2 p0 = *reinterpret_cast<__half2*>(&raw.x);
    __half2 p1 = *reinterpret_cast<__half2*>(&raw.y);
    float2 f0 = __half22float2(p0);
    float2 f1 = __half22float2(p1);
    acc.x = fmaf(w, f0.x, acc.x);
    acc.y = fmaf(w, f0.y, acc.y);
    acc.z = fmaf(w, f1.x, acc.z);
    acc.w = fmaf(w, f1.y, acc.w);
}

// out[c] = [relu]( dinv[c] * ( sum_{r in N(c)} dinv[r]*u[r] + dinv[c]*u[c] ) + b )
template <int L, bool RELU, bool HOUT>
__global__ void aggregate_h(const int* __restrict__ rowptr, const int* __restrict__ csr,
                            const __half* __restrict__ Gh, const float* __restrict__ dinv,
                            const float4* __restrict__ bias, void* __restrict__ outv)
{
    constexpr int RS = L * 4;
    const int node = (blockIdx.x * blockDim.x + threadIdx.x) / L;
    const int lane = threadIdx.x % L;

    const float ds = dinv[node];
    float4 acc = make_float4(0.f, 0.f, 0.f, 0.f);
    {
        uint2 raw = *reinterpret_cast<const uint2*>(&Gh[(size_t)node * RS + lane * 4]);
        acc_half4(acc, ds, raw);
    }

    const int start = rowptr[node];
    const int end   = rowptr[node + 1];

    int idx = 0; float dd = 0.f;
    if (start + lane < end) { int t = csr[start + lane]; idx = t; dd = dinv[t]; }

    for (int p = start; p < end; p += L) {
        const int m = min(L, end - p);
        int nidx = 0; float ndd = 0.f;
        if (p + L + lane < end) { int t = csr[p + L + lane]; nidx = t; ndd = dinv[t]; }

        int j = 0;
        for (; j + 4 <= m; j += 4) {
            int   r0 = __shfl_sync(0xffffffffu, idx, j + 0, L);
            int   r1 = __shfl_sync(0xffffffffu, idx, j + 1, L);
            int   r2 = __shfl_sync(0xffffffffu, idx, j + 2, L);
            int   r3 = __shfl_sync(0xffffffffu, idx, j + 3, L);
            float w0 = __shfl_sync(0xffffffffu, dd,  j + 0, L);
            float w1 = __shfl_sync(0xffffffffu, dd,  j + 1, L);
            float w2 = __shfl_sync(0xffffffffu, dd,  j + 2, L);
            float w3 = __shfl_sync(0xffffffffu, dd,  j + 3, L);
            uint2 a = *reinterpret_cast<const uint2*>(&Gh[(size_t)r0 * RS + lane * 4]);
            uint2 b = *reinterpret_cast<const uint2*>(&Gh[(size_t)r1 * RS + lane * 4]);
            uint2 c = *reinterpret_cast<const uint2*>(&Gh[(size_t)r2 * RS + lane * 4]);
            uint2 d = *reinterpret_cast<const uint2*>(&Gh[(size_t)r3 * RS + lane * 4]);
            acc_half4(acc, w0, a);
            acc_half4(acc, w1, b);
            acc_half4(acc, w2, c);
            acc_half4(acc, w3, d);
        }
        for (; j < m; j++) {
            int   r = __shfl_sync(0xffffffffu, idx, j, L);
            float w = __shfl_sync(0xffffffffu, dd,  j, L);
            uint2 a = *reinterpret_cast<const uint2*>(&Gh[(size_t)r * RS + lane * 4]);
            acc_half4(acc, w, a);
        }
        idx = nidx; dd = ndd;
    }

    float4 bb = bias[lane];
    float4 r;
    r.x = fmaf(ds, acc.x, bb.x);
    r.y = fmaf(ds, acc.y, bb.y);
    r.z = fmaf(ds, acc.z, bb.z);
    r.w = fmaf(ds, acc.w, bb.w);
    if (RELU) {
        r.x = fmaxf(r.x, 0.f); r.y = fmaxf(r.y, 0.f);
        r.z = fmaxf(r.z, 0.f); r.w = fmaxf(r.w, 0.f);
    }
    if (HOUT) {
        __half2 h0 = __floats2half2_rn(r.x, r.y);
        __half2 h1 = __floats2half2_rn(r.z, r.w);
        uint2 o;
        o.x = *reinterpret_cast<unsigned*>(&h0);
        o.y = *reinterpret_cast<unsigned*>(&h1);
        reinterpret_cast<uint2*>(outv)[(size_t)node * L + lane] = o;
    } else {
        reinterpret_cast<float4*>(outv)[(size_t)node * L + lane] = r;
    }
}

// ---------------- launch ----------------
extern "C" void kernel_launch(void* const* d_in, const int* in_sizes, int n_in,
                              void* d_out, int out_size)
{
    const float* x  = (const float*)d_in[0];
    const int*   ei = (const int*)  d_in[1];
    const float* W1 = (const float*)d_in[2];
    const float* b1 = (const float*)d_in[3];
    const float* W2 = (const float*)d_in[4];
    const float* b2 = (const float*)d_in[5];
    float* out = (float*)d_out;

    int *degi, *cur, *rowptr, *csr;
    unsigned long long* desc;
    float *dinv;
    __half *wt1, *wt2, *u1h, *h, *u2h;
    cudaGetSymbolAddress((void**)&degi,   g_degi);
    cudaGetSymbolAddress((void**)&cur,    g_cur);
    cudaGetSymbolAddress((void**)&rowptr, g_rowptr);
    cudaGetSymbolAddress((void**)&csr,    g_csr);
    cudaGetSymbolAddress((void**)&desc,   g_desc);
    cudaGetSymbolAddress((void**)&dinv,   g_dinv);
    cudaGetSymbolAddress((void**)&wt1,    g_wt1);
    cudaGetSymbolAddress((void**)&wt2,    g_wt2);
    cudaGetSymbolAddress((void**)&u1h,    g_u1h);
    cudaGetSymbolAddress((void**)&h,      g_h);
    cudaGetSymbolAddress((void**)&u2h,    g_u2h);

    static cudaStream_t s1 = nullptr;
    static cudaEvent_t  evFork = nullptr, evJoin = nullptr;
    if (!s1) {
        cudaStreamCreateWithFlags(&s1, cudaStreamNonBlocking);
        cudaEventCreateWithFlags(&evFork, cudaEventDisableTiming);
        cudaEventCreateWithFlags(&evJoin, cudaEventDisableTiming);
    }

    const int T = 256;

    // ---- fork: CSR build chain on s1 ----
    cudaEventRecord(evFork, 0);
    cudaStreamWaitEvent(s1, evFork, 0);

    zero2     <<<(N_NODES + T - 1) / T, T, 0, s1>>>(degi, desc);
    deg_accum4<<<(N_EDGES / 4 + T - 1) / T, T, 0, s1>>>(
        (const int4*)(ei + N_EDGES), degi);
    scan_rowptr<<<NB_SCAN, 256, 0, s1>>>(degi, dinv, rowptr, cur, desc);
    csr_fill4 <<<(N_EDGES / 4 + T - 1) / T, T, 0, s1>>>(
        (const int4*)ei, (const int4*)(ei + N_EDGES), cur, csr);

    // ---- main stream: weight converts + GEMM1 (x converted inside tile load) ----
    conv_wt<<<(INDIM * HIDIM + T - 1) / T, T>>>(W1, wt1, INDIM, HIDIM);
    conv_wt<<<(HIDIM * OUTDIM + T - 1) / T, T>>>(W2, wt2, HIDIM, OUTDIM);

    gemm_mma<INDIM, HIDIM, true>
        <<<(N_NODES + 127) / 128, 256>>>((const void*)x, wt1, u1h, N_NODES);

    // ---- join ----
    cudaEventRecord(evJoin, s1);
    cudaStreamWaitEvent(0, evJoin, 0);

    // layer 1 aggregate -> h (fp16)
    aggregate_h<32, true, true><<<N_NODES / 8, 256>>>(
        rowptr, csr, u1h, dinv, (const float4*)b1, (void*)h);

    // layer 2
    gemm_mma<HIDIM, OUTDIM, false>
        <<<(N_NODES + 127) / 128, 256>>>((const void*)h, wt2, u2h, N_NODES);
    aggregate_h<16, false, false><<<N_NODES / 16, 256>>>(
        rowptr, csr, u2h, dinv, (const float4*)b2, (void*)out);
}

// round 7
// speedup vs baseline: 2.8635x; 1.0114x over previous
#include <cuda_runtime.h>
#include <cuda_fp16.h>
#include <cstddef>
#include <cstdint>

#define N_NODES 50000
#define N_EDGES 1600000
#define INDIM   256
#define HIDIM   128
#define OUTDIM  64
#define NB_SCAN ((N_NODES + 256) / 256)   // 196

// ---------------- scratch (allocation-free: __device__ globals) ----------------
__device__ int    g_degi  [N_NODES];
__device__ int    g_pos   [N_EDGES];        // slot of edge within its dst bucket
__device__ int    g_rowptr[N_NODES + 1];
__device__ int    g_csr   [N_EDGES];
__device__ unsigned long long g_desc[NB_SCAN];
__device__ float  g_dinv  [N_NODES];
__device__ __half g_wt1   [(size_t)HIDIM * INDIM];     // W1^T fp16 [128][256]
__device__ __half g_wt2   [(size_t)OUTDIM * HIDIM];    // W2^T fp16 [64][128]
__device__ __half g_u1h   [(size_t)N_NODES * HIDIM];   // x @ W1 (fp16)
__device__ __half g_h     [(size_t)N_NODES * HIDIM];   // layer1 out (fp16)
__device__ __half g_u2h   [(size_t)N_NODES * OUTDIM];  // h @ W2 (fp16)

// ---------------- CSR build kernels ----------------
__global__ void zero2(int* degi, unsigned long long* desc) {
    int i = blockIdx.x * blockDim.x + threadIdx.x;
    if (i < N_NODES) degi[i] = 0;
    if (i < NB_SCAN) desc[i] = 0ULL;
}

// degree count + per-edge bucket slot (atomic return), 4 edges/thread
__global__ void deg_pos4(const int4* __restrict__ col4, int* __restrict__ degi,
                         int4* __restrict__ pos4) {
    int i = blockIdx.x * blockDim.x + threadIdx.x;
    if (i >= N_EDGES / 4) return;
    int4 c = col4[i];
    int4 p;
    p.x = atomicAdd(&degi[c.x], 1);
    p.y = atomicAdd(&degi[c.y], 1);
    p.z = atomicAdd(&degi[c.z], 1);
    p.w = atomicAdd(&degi[c.w], 1);
    pos4[i] = p;
}

// single-pass scan with PARALLEL lookback (all 196 blocks co-resident).
// Also writes dinv.
__global__ void scan_rowptr(const int* __restrict__ degi, float* __restrict__ dinv,
                            int* __restrict__ rowptr,
                            volatile unsigned long long* desc)
{
    __shared__ int sh[256];
    __shared__ int red[256];
    const int b = blockIdx.x, t = threadIdx.x;
    const int i = b * 256 + t;

    int v = (i < N_NODES) ? degi[i] : 0;
    if (i < N_NODES) dinv[i] = rsqrtf((float)v + 1.0f);   // +1 self loop

    sh[t] = v;
    __syncthreads();
    #pragma unroll
    for (int off = 1; off < 256; off <<= 1) {
        int x = (t >= off) ? sh[t - off] : 0;
        __syncthreads();
        sh[t] += x;
        __syncthreads();
    }
    const int incl  = sh[t];
    const int total = sh[255];

    if (t == 0) desc[b] = (1ULL << 32) | (unsigned)total;

    int contrib = 0;
    if (t < b) {
        unsigned long long d;
        do { d = desc[t]; } while ((d >> 32) == 0ULL);
        contrib = (int)(unsigned)d;
    }
    red[t] = contrib;
    __syncthreads();
    #pragma unroll
    for (int s = 128; s > 0; s >>= 1) {
        if (t < s) red[t] += red[t + s];
        __syncthreads();
    }
    const int off = red[0];

    if (i <= N_NODES) rowptr[i] = off + incl - v;   // exclusive prefix
}

// atomic-free fill: csr[rowptr[col] + pos] = row
__global__ void csr_fill4(const int4* __restrict__ row4, const int4* __restrict__ col4,
                          const int4* __restrict__ pos4,
                          const int* __restrict__ rowptr, int* __restrict__ csr) {
    int i = blockIdx.x * blockDim.x + threadIdx.x;
    if (i >= N_EDGES / 4) return;
    int4 r = row4[i];
    int4 c = col4[i];
    int4 p = pos4[i];
    int b0 = __ldg(&rowptr[c.x]);
    int b1 = __ldg(&rowptr[c.y]);
    int b2 = __ldg(&rowptr[c.z]);
    int b3 = __ldg(&rowptr[c.w]);
    csr[b0 + p.x] = r.x;
    csr[b1 + p.y] = r.y;
    csr[b2 + p.z] = r.z;
    csr[b3 + p.w] = r.w;
}

// ---------------- fused weight transpose/convert (both layers) ----------------
// W1 [256][128] -> Wt1 [128][256];  W2 [128][64] -> Wt2 [64][128]
__global__ void conv_wt_both(const float* __restrict__ W1, __half* __restrict__ Wt1,
                             const float* __restrict__ W2, __half* __restrict__ Wt2) {
    int o = blockIdx.x * blockDim.x + threadIdx.x;
    const int n1 = INDIM * HIDIM;
    if (o < n1) {
        int m = o / INDIM, k = o % INDIM;
        Wt1[o] = __float2half(W1[(size_t)k * HIDIM + m]);
    }
    int o2 = o - n1;
    if (o2 >= 0 && o2 < HIDIM * OUTDIM) {
        int m = o2 / HIDIM, k = o2 % HIDIM;
        Wt2[o2] = __float2half(W2[(size_t)k * OUTDIM + m]);
    }
}

// ---------------- tensor-core fp16 GEMM: out = A @ Bt^T ----------------
__device__ __forceinline__ void mma16816(float* c, const unsigned* a,
                                         unsigned b0, unsigned b1) {
    asm volatile(
        "mma.sync.aligned.m16n8k16.row.col.f32.f16.f16.f32 "
        "{%0,%1,%2,%3}, {%4,%5,%6,%7}, {%8,%9}, {%0,%1,%2,%3};"
        : "+f"(c[0]), "+f"(c[1]), "+f"(c[2]), "+f"(c[3])
        : "r"(a[0]), "r"(a[1]), "r"(a[2]), "r"(a[3]), "r"(b0), "r"(b1));
}

template <int K, int BN, bool AF32>
__global__ void __launch_bounds__(256)
gemm_mma(const void* __restrict__ Av, const __half* __restrict__ Bt,
         __half* __restrict__ out, int n)
{
    constexpr int BM  = 128;
    constexpr int BK  = 32;
    constexpr int PAD = 40;
    constexpr int WN  = BN / 2;
    constexpr int NT  = WN / 8;
    constexpr int AL  = (BM * 8) / 256;
    constexpr int BL  = (BN * 8) / 256;

    __shared__ __half As[2][BM][PAD];
    __shared__ __half Bs[2][BN][PAD];

    const int tid  = threadIdx.x;
    const int lane = tid & 31;
    const int wid  = tid >> 5;
    const int wr   = wid & 3;
    const int wc   = wid >> 2;
    const int rowBase = blockIdx.x * BM;

    const int r4 = lane >> 2;
    const int c2 = (lane & 3) * 2;

    float acc[2][NT][4];
    #pragma unroll
    for (int mt = 0; mt < 2; mt++)
        #pragma unroll
        for (int nt = 0; nt < NT; nt++)
            #pragma unroll
            for (int q = 0; q < 4; q++) acc[mt][nt][q] = 0.f;

    uint2 abuf[AL], bbuf[BL];

    auto loadA = [&](int k0) {
        #pragma unroll
        for (int i = 0; i < AL; i++) {
            int idx = tid + i * 256;
            int r = idx >> 3, sg = idx & 7;
            int gr = rowBase + r;
            uint2 v = make_uint2(0u, 0u);
            if (gr < n) {
                if (AF32) {
                    float4 f = *reinterpret_cast<const float4*>(
                        (const float*)Av + (size_t)gr * K + k0 + sg * 4);
                    __half2 h0 = __floats2half2_rn(f.x, f.y);
                    __half2 h1 = __floats2half2_rn(f.z, f.w);
                    v.x = *reinterpret_cast<unsigned*>(&h0);
                    v.y = *reinterpret_cast<unsigned*>(&h1);
                } else {
                    v = *reinterpret_cast<const uint2*>(
                        (const __half*)Av + (size_t)gr * K + k0 + sg * 4);
                }
            }
            abuf[i] = v;
        }
    };
    auto loadB = [&](int k0) {
        #pragma unroll
        for (int i = 0; i < BL; i++) {
            int idx = tid + i * 256;
            int r = idx >> 3, sg = idx & 7;
            bbuf[i] = *reinterpret_cast<const uint2*>(&Bt[(size_t)r * K + k0 + sg * 4]);
        }
    };
    auto store = [&](int s) {
        #pragma unroll
        for (int i = 0; i < AL; i++) {
            int idx = tid + i * 256;
            int r = idx >> 3, sg = idx & 7;
            *reinterpret_cast<uint2*>(&As[s][r][sg * 4]) = abuf[i];
        }
        #pragma unroll
        for (int i = 0; i < BL; i++) {
            int idx = tid + i * 256;
            int r = idx >> 3, sg = idx & 7;
            *reinterpret_cast<uint2*>(&Bs[s][r][sg * 4]) = bbuf[i];
        }
    };

    loadA(0); loadB(0);
    store(0);
    __syncthreads();

    constexpr int NSTEP = K / BK;
    #pragma unroll
    for (int step = 0; step < NSTEP; step++) {
        const int s = step & 1;
        if (step + 1 < NSTEP) { loadA((step + 1) * BK); loadB((step + 1) * BK); }

        #pragma unroll
        for (int ks = 0; ks < BK; ks += 16) {
            unsigned a[2][4];
            #pragma unroll
            for (int mt = 0; mt < 2; mt++) {
                int m0 = wr * 32 + mt * 16;
                a[mt][0] = *reinterpret_cast<const unsigned*>(&As[s][m0 + r4    ][ks + c2    ]);
                a[mt][1] = *reinterpret_cast<const unsigned*>(&As[s][m0 + r4 + 8][ks + c2    ]);
                a[mt][2] = *reinterpret_cast<const unsigned*>(&As[s][m0 + r4    ][ks + c2 + 8]);
                a[mt][3] = *reinterpret_cast<const unsigned*>(&As[s][m0 + r4 + 8][ks + c2 + 8]);
            }
            #pragma unroll
            for (int nt = 0; nt < NT; nt++) {
                int n0 = wc * WN + nt * 8;
                unsigned b0 = *reinterpret_cast<const unsigned*>(&Bs[s][n0 + r4][ks + c2    ]);
                unsigned b1 = *reinterpret_cast<const unsigned*>(&Bs[s][n0 + r4][ks + c2 + 8]);
                mma16816(acc[0][nt], a[0], b0, b1);
                mma16816(acc[1][nt], a[1], b0, b1);
            }
        }
        __syncthreads();
        if (step + 1 < NSTEP) {
            store(s ^ 1);
            __syncthreads();
        }
    }

    #pragma unroll
    for (int mt = 0; mt < 2; mt++) {
        #pragma unroll
        for (int nt = 0; nt < NT; nt++) {
            int row0 = rowBase + wr * 32 + mt * 16 + r4;
            int col  = wc * WN + nt * 8 + c2;
            if (row0 < n) {
                __half2 h = __floats2half2_rn(acc[mt][nt][0], acc[mt][nt][1]);
                *reinterpret_cast<unsigned*>(&out[(size_t)row0 * BN + col]) =
                    *reinterpret_cast<unsigned*>(&h);
            }
            if (row0 + 8 < n) {
                __half2 h = __floats2half2_rn(acc[mt][nt][2], acc[mt][nt][3]);
                *reinterpret_cast<unsigned*>(&out[(size_t)(row0 + 8) * BN + col]) =
                    *reinterpret_cast<unsigned*>(&h);
            }
        }
    }
}

// ---------------- CSR gather-aggregate over fp16 messages ----------------
__device__ __forceinline__ void acc_half4(float4& acc, float w, uint2 raw) {
    __half2 p0 = *reinterpret_cast<__half2*>(&raw.x);
    __half2 p1 = *reinterpret_cast<__half2*>(&raw.y);
    float2 f0 = __half22float2(p0);
    float2 f1 = __half22float2(p1);
    acc.x = fmaf(w, f0.x, acc.x);
    acc.y = fmaf(w, f0.y, acc.y);
    acc.z = fmaf(w, f1.x, acc.z);
    acc.w = fmaf(w, f1.y, acc.w);
}

// out[c] = [relu]( dinv[c] * ( sum_{r in N(c)} dinv[r]*u[r] + dinv[c]*u[c] ) + b )
template <int L, bool RELU, bool HOUT>
__global__ void aggregate_h(const int* __restrict__ rowptr, const int* __restrict__ csr,
                            const __half* __restrict__ Gh, const float* __restrict__ dinv,
                            const float4* __restrict__ bias, void* __restrict__ outv)
{
    constexpr int RS = L * 4;
    const int node = (blockIdx.x * blockDim.x + threadIdx.x) / L;
    const int lane = threadIdx.x % L;

    const float ds = dinv[node];
    float4 acc = make_float4(0.f, 0.f, 0.f, 0.f);
    {
        uint2 raw = *reinterpret_cast<const uint2*>(&Gh[(size_t)node * RS + lane * 4]);
        acc_half4(acc, ds, raw);
    }

    const int start = rowptr[node];
    const int end   = rowptr[node + 1];

    int idx = 0; float dd = 0.f;
    if (start + lane < end) { int t = csr[start + lane]; idx = t; dd = dinv[t]; }

    for (int p = start; p < end; p += L) {
        const int m = min(L, end - p);
        int nidx = 0; float ndd = 0.f;
        if (p + L < end && p + L + lane < end) {
            int t = csr[p + L + lane]; nidx = t; ndd = dinv[t];
        }

        int j = 0;
        for (; j + 4 <= m; j += 4) {
            int   r0 = __shfl_sync(0xffffffffu, idx, j + 0, L);
            int   r1 = __shfl_sync(0xffffffffu, idx, j + 1, L);
            int   r2 = __shfl_sync(0xffffffffu, idx, j + 2, L);
            int   r3 = __shfl_sync(0xffffffffu, idx, j + 3, L);
            float w0 = __shfl_sync(0xffffffffu, dd,  j + 0, L);
            float w1 = __shfl_sync(0xffffffffu, dd,  j + 1, L);
            float w2 = __shfl_sync(0xffffffffu, dd,  j + 2, L);
            float w3 = __shfl_sync(0xffffffffu, dd,  j + 3, L);
            uint2 a = *reinterpret_cast<const uint2*>(&Gh[(size_t)r0 * RS + lane * 4]);
            uint2 b = *reinterpret_cast<const uint2*>(&Gh[(size_t)r1 * RS + lane * 4]);
            uint2 c = *reinterpret_cast<const uint2*>(&Gh[(size_t)r2 * RS + lane * 4]);
            uint2 d = *reinterpret_cast<const uint2*>(&Gh[(size_t)r3 * RS + lane * 4]);
            acc_half4(acc, w0, a);
            acc_half4(acc, w1, b);
            acc_half4(acc, w2, c);
            acc_half4(acc, w3, d);
        }
        for (; j < m; j++) {
            int   r = __shfl_sync(0xffffffffu, idx, j, L);
            float w = __shfl_sync(0xffffffffu, dd,  j, L);
            uint2 a = *reinterpret_cast<const uint2*>(&Gh[(size_t)r * RS + lane * 4]);
            acc_half4(acc, w, a);
        }
        idx = nidx; dd = ndd;
    }

    float4 bb = bias[lane];
    float4 r;
    r.x = fmaf(ds, acc.x, bb.x);
    r.y = fmaf(ds, acc.y, bb.y);
    r.z = fmaf(ds, acc.z, bb.z);
    r.w = fmaf(ds, acc.w, bb.w);
    if (RELU) {
        r.x = fmaxf(r.x, 0.f); r.y = fmaxf(r.y, 0.f);
        r.z = fmaxf(r.z, 0.f); r.w = fmaxf(r.w, 0.f);
    }
    if (HOUT) {
        __half2 h0 = __floats2half2_rn(r.x, r.y);
        __half2 h1 = __floats2half2_rn(r.z, r.w);
        uint2 o;
        o.x = *reinterpret_cast<unsigned*>(&h0);
        o.y = *reinterpret_cast<unsigned*>(&h1);
        reinterpret_cast<uint2*>(outv)[(size_t)node * L + lane] = o;
    } else {
        reinterpret_cast<float4*>(outv)[(size_t)node * L + lane] = r;
    }
}

// ---------------- launch ----------------
extern "C" void kernel_launch(void* const* d_in, const int* in_sizes, int n_in,
                              void* d_out, int out_size)
{
    const float* x  = (const float*)d_in[0];
    const int*   ei = (const int*)  d_in[1];
    const float* W1 = (const float*)d_in[2];
    const float* b1 = (const float*)d_in[3];
    const float* W2 = (const float*)d_in[4];
    const float* b2 = (const float*)d_in[5];
    float* out = (float*)d_out;

    int *degi, *pos, *rowptr, *csr;
    unsigned long long* desc;
    float *dinv;
    __half *wt1, *wt2, *u1h, *h, *u2h;
    cudaGetSymbolAddress((void**)&degi,   g_degi);
    cudaGetSymbolAddress((void**)&pos,    g_pos);
    cudaGetSymbolAddress((void**)&rowptr, g_rowptr);
    cudaGetSymbolAddress((void**)&csr,    g_csr);
    cudaGetSymbolAddress((void**)&desc,   g_desc);
    cudaGetSymbolAddress((void**)&dinv,   g_dinv);
    cudaGetSymbolAddress((void**)&wt1,    g_wt1);
    cudaGetSymbolAddress((void**)&wt2,    g_wt2);
    cudaGetSymbolAddress((void**)&u1h,    g_u1h);
    cudaGetSymbolAddress((void**)&h,      g_h);
    cudaGetSymbolAddress((void**)&u2h,    g_u2h);

    static cudaStream_t s1 = nullptr;
    static cudaEvent_t  evFork = nullptr, evJoin = nullptr;
    if (!s1) {
        cudaStreamCreateWithFlags(&s1, cudaStreamNonBlocking);
        cudaEventCreateWithFlags(&evFork, cudaEventDisableTiming);
        cudaEventCreateWithFlags(&evJoin, cudaEventDisableTiming);
    }

    const int T = 256;

    // ---- fork: CSR build chain on s1 ----
    cudaEventRecord(evFork, 0);
    cudaStreamWaitEvent(s1, evFork, 0);

    zero2    <<<(N_NODES + T - 1) / T, T, 0, s1>>>(degi, desc);
    deg_pos4 <<<(N_EDGES / 4 + T - 1) / T, T, 0, s1>>>(
        (const int4*)(ei + N_EDGES), degi, (int4*)pos);
    scan_rowptr<<<NB_SCAN, 256, 0, s1>>>(degi, dinv, rowptr, desc);
    csr_fill4<<<(N_EDGES / 4 + T - 1) / T, T, 0, s1>>>(
        (const int4*)ei, (const int4*)(ei + N_EDGES), (const int4*)pos,
        rowptr, csr);

    // ---- main stream: weight convert + GEMM1 (x converted inside tile load) ----
    conv_wt_both<<<(INDIM * HIDIM + HIDIM * OUTDIM + T - 1) / T, T>>>(W1, wt1, W2, wt2);

    gemm_mma<INDIM, HIDIM, true>
        <<<(N_NODES + 127) / 128, 256>>>((const void*)x, wt1, u1h, N_NODES);

    // ---- join ----
    cudaEventRecord(evJoin, s1);
    cudaStreamWaitEvent(0, evJoin, 0);

    // layer 1 aggregate -> h (fp16)
    aggregate_h<32, true, true><<<N_NODES / 8, 256>>>(
        rowptr, csr, u1h, dinv, (const float4*)b1, (void*)h);

    // layer 2
    gemm_mma<HIDIM, OUTDIM, false>
        <<<(N_NODES + 127) / 128, 256>>>((const void*)h, wt2, u2h, N_NODES);
    aggregate_h<16, false, false><<<N_NODES / 16, 256>>>(
        rowptr, csr, u2h, dinv, (const float4*)b2, (void*)out);
}